// round 8
// baseline (speedup 1.0000x reference)
#include <cuda_runtime.h>
#include <cuda_bf16.h>
#include <math.h>
#include <stdint.h>

#define BB 16
#define TT 600
#define VV 20000
#define EE 300
#define HH 512
#define BT (BB*TT)   // 9600

// ---------------- scratch ----------------
__device__ uint32_t g_A2h[(size_t)BT*256];   // enc hi, bf16 [9600][512] packed as u32
__device__ uint32_t g_A2l[(size_t)BT*256];   // enc lo
__device__ uint32_t g_Wth[1024*256];         // W^T hi, bf16 [1024 n][512 k]
__device__ uint32_t g_Wtl[1024*256];         // W^T lo
__device__ uint32_t g_encb[(size_t)BB*TT*VV/2];  // enc_ins bf16 [16][600][20000], 384MB
__device__ float g_z1[BB*2048];
__device__ float g_z2[BB*2048];
__device__ float g_q[BB*1024];
__device__ float g_ha[BB*HH];
__device__ float g_sg[BB*TT];
__device__ float g_sc[BB*TT];
__device__ float g_aligng[BB*TT];
__device__ float g_alignc[BB*TT];
__device__ float g_ctx[BB*HH];
__device__ float g_logits[(size_t)BB*VV];
__device__ float g_pm[BB*10];
__device__ float g_ps[BB*10];
__device__ float g_vred[BB*2];
__device__ float g_switch[BB];

__device__ __forceinline__ float sigf(float x){ return 1.0f/(1.0f+expf(-x)); }

// ---------------- init: biases / zeros into accumulators ----------------
#define INIT_TOTAL (117504 + 320000)
__global__ void init_kernel(const float* __restrict__ b1, const float* __restrict__ b2,
                            const float* __restrict__ bh, const float* __restrict__ bg) {
  int idx = blockIdx.x*blockDim.x + threadIdx.x;
  if (idx < 32768)            g_z1[idx] = b1[idx & 2047];
  else if (idx < 65536)       g_z2[idx-32768] = b2[idx & 2047];
  else if (idx < 81920)       g_q[idx-65536] = 0.f;
  else if (idx < 90112)       g_ha[idx-81920] = bh[idx & 511];
  else if (idx < 98304)       g_ctx[idx-90112] = 0.f;
  else if (idx < 107904)      g_sg[idx-98304] = 0.f;
  else if (idx < 117504)      g_sc[idx-107904] = 0.f;
  else if (idx < INIT_TOTAL) {
    int e = idx - 117504;
    g_logits[e] = bg[e % VV];
  }
}

// ---------------- convert enc_outs -> bf16 hi/lo ----------------
__global__ void convA_kernel(const float* __restrict__ A) {
  int i4 = blockIdx.x*blockDim.x + threadIdx.x;
  if (i4 >= BT*512/4) return;
  float4 v = *(const float4*)&A[i4*4];
  __nv_bfloat16 h0 = __float2bfloat16(v.x);
  __nv_bfloat16 h1 = __float2bfloat16(v.y);
  __nv_bfloat16 h2 = __float2bfloat16(v.z);
  __nv_bfloat16 h3 = __float2bfloat16(v.w);
  __nv_bfloat16 l0 = __float2bfloat16(v.x - __bfloat162float(h0));
  __nv_bfloat16 l1 = __float2bfloat16(v.y - __bfloat162float(h1));
  __nv_bfloat16 l2 = __float2bfloat16(v.z - __bfloat162float(h2));
  __nv_bfloat16 l3 = __float2bfloat16(v.w - __bfloat162float(h3));
  __nv_bfloat162* ph = (__nv_bfloat162*)g_A2h;
  __nv_bfloat162* pl = (__nv_bfloat162*)g_A2l;
  ph[i4*2]   = __nv_bfloat162(h0,h1);
  ph[i4*2+1] = __nv_bfloat162(h2,h3);
  pl[i4*2]   = __nv_bfloat162(l0,l1);
  pl[i4*2+1] = __nv_bfloat162(l2,l3);
}

// ---------------- transpose + convert W -> Wt bf16 hi/lo ----------------
__global__ void convW_kernel(const float* __restrict__ Wg, const float* __restrict__ Wc) {
  __shared__ float tile[32][33];
  int k0 = blockIdx.x*32;
  int n0 = blockIdx.y*32;
  const float* W = (n0 < 512) ? Wg : Wc;
  int nn0 = n0 & 511;
  int tx = threadIdx.x & 31, ty = threadIdx.x >> 5;
  #pragma unroll
  for (int i=0;i<4;i++) {
    int k = k0 + ty + i*8;
    tile[ty+i*8][tx] = W[(size_t)k*512 + nn0 + tx];
  }
  __syncthreads();
  __nv_bfloat16* WH = (__nv_bfloat16*)g_Wth;
  __nv_bfloat16* WL = (__nv_bfloat16*)g_Wtl;
  #pragma unroll
  for (int i=0;i<4;i++) {
    int n = n0 + ty + i*8;
    float x = tile[tx][ty+i*8];
    __nv_bfloat16 h = __float2bfloat16(x);
    WH[(size_t)n*512 + k0 + tx] = h;
    WL[(size_t)n*512 + k0 + tx] = __float2bfloat16(x - __bfloat162float(h));
  }
}

// ---------------- convert enc_ins -> bf16 (runs overlapped, low-prio stream) ----------------
__global__ void convEnc_kernel(const float* __restrict__ E) {
  size_t i = (size_t)blockIdx.x*blockDim.x + threadIdx.x;
  size_t stride = (size_t)gridDim.x*blockDim.x;
  const float4* E4 = (const float4*)E;
  uint2* O = (uint2*)g_encb;
  size_t n4 = (size_t)BB*TT*VV/4;
  for (size_t j = i; j < n4; j += stride) {
    float4 v = E4[j];
    __nv_bfloat162 p0 = __floats2bfloat162_rn(v.x, v.y);
    __nv_bfloat162 p1 = __floats2bfloat162_rn(v.z, v.w);
    uint2 o;
    o.x = *(uint32_t*)&p0;
    o.y = *(uint32_t*)&p1;
    O[j] = o;
  }
}

// ---------------- mma helpers ----------------
__device__ __forceinline__ void mma16816(float* c, const uint32_t* a, const uint32_t* b) {
  asm volatile(
    "mma.sync.aligned.m16n8k16.row.col.f32.bf16.bf16.f32 "
    "{%0,%1,%2,%3}, {%4,%5,%6,%7}, {%8,%9}, {%0,%1,%2,%3};"
    : "+f"(c[0]), "+f"(c[1]), "+f"(c[2]), "+f"(c[3])
    : "r"(a[0]), "r"(a[1]), "r"(a[2]), "r"(a[3]), "r"(b[0]), "r"(b[1]));
}

__device__ __forceinline__ void ldm_x4(uint32_t* r, uint32_t addr) {
  asm volatile("ldmatrix.sync.aligned.m8n8.x4.shared.b16 {%0,%1,%2,%3}, [%4];"
    : "=r"(r[0]), "=r"(r[1]), "=r"(r[2]), "=r"(r[3]) : "r"(addr));
}

// ---------------- fused: P = enc @ [aw2g|aw2c]; scores += tanh(q+P)*av ----------------
__global__ void __launch_bounds__(256, 2) mma_attn_scores_kernel(
    const float* __restrict__ avg, const float* __restrict__ avc) {
  __shared__ uint32_t sAh[128*20];
  __shared__ uint32_t sAl[128*20];
  __shared__ uint32_t sBh[128*20];
  __shared__ uint32_t sBl[128*20];
  __shared__ float s_av[128];
  __shared__ float s_q[2][128];

  int tid = threadIdx.x;
  int bm = blockIdx.x * 128;     // 75
  int bn = blockIdx.y * 128;     // 8
  int wid = tid >> 5, lane = tid & 31;
  int wm = wid >> 1, wn = wid & 1;
  int g = lane >> 2, t4 = lane & 3;

  int b_lo = bm / 600;
  int b_hi = (bm + 127) / 600;
  if (tid < 128) {
    const float* av = (bn < 512) ? avg : avc;
    s_av[tid] = av[(bn & 511) + tid];
    s_q[0][tid] = g_q[b_lo*1024 + bn + tid];
    s_q[1][tid] = g_q[b_hi*1024 + bn + tid];
  }

  uint32_t baseAh = (uint32_t)__cvta_generic_to_shared(sAh);
  uint32_t baseAl = (uint32_t)__cvta_generic_to_shared(sAl);
  uint32_t baseBh = (uint32_t)__cvta_generic_to_shared(sBh);
  uint32_t baseBl = (uint32_t)__cvta_generic_to_shared(sBl);
  uint32_t aoff = ((uint32_t)((wm*32 + (lane & 15))*20 + (lane >> 4)*4)) * 4;
  uint32_t aAh0 = baseAh + aoff, aAl0 = baseAl + aoff;
  uint32_t boff = ((uint32_t)((wn*64 + (lane & 7) + ((lane >> 4) << 3))*20 + ((lane >> 3) & 1)*4)) * 4;
  uint32_t bBh0 = baseBh + boff, bBl0 = baseBl + boff;

  float acc[2][8][4];
  #pragma unroll
  for (int mt=0;mt<2;mt++)
    #pragma unroll
    for (int nt=0;nt<8;nt++)
      #pragma unroll
      for (int r=0;r<4;r++) acc[mt][nt][r]=0.f;

  for (int kc=0; kc<512; kc+=32) {
    #pragma unroll
    for (int i=0;i<8;i++) {
      int e = tid + i*256;
      int row = e >> 4, kw = e & 15;
      size_t ga = (size_t)(bm+row)*256 + (kc>>1) + kw;
      size_t gb = (size_t)(bn+row)*256 + (kc>>1) + kw;
      int ss = row*20 + kw;
      sAh[ss] = g_A2h[ga];
      sAl[ss] = g_A2l[ga];
      sBh[ss] = g_Wth[gb];
      sBl[ss] = g_Wtl[gb];
    }
    __syncthreads();

    #pragma unroll
    for (int ks=0; ks<2; ks++) {
      uint32_t kb = ks*32;
      uint32_t ah[2][4], al[2][4];
      ldm_x4(ah[0], aAh0 + kb);
      ldm_x4(ah[1], aAh0 + 1280 + kb);
      ldm_x4(al[0], aAl0 + kb);
      ldm_x4(al[1], aAl0 + 1280 + kb);
      #pragma unroll
      for (int ntp=0; ntp<4; ntp++) {
        uint32_t bh4[4], bl4[4];
        ldm_x4(bh4, bBh0 + (uint32_t)ntp*1280 + kb);
        ldm_x4(bl4, bBl0 + (uint32_t)ntp*1280 + kb);
        int n0 = ntp*2, n1 = ntp*2+1;
        #pragma unroll
        for (int mt=0;mt<2;mt++) {
          mma16816(acc[mt][n0], ah[mt], bh4+0);
          mma16816(acc[mt][n0], ah[mt], bl4+0);
          mma16816(acc[mt][n0], al[mt], bh4+0);
          mma16816(acc[mt][n1], ah[mt], bh4+2);
          mma16816(acc[mt][n1], ah[mt], bl4+2);
          mma16816(acc[mt][n1], al[mt], bh4+2);
        }
      }
    }
    __syncthreads();
  }

  float* dst = (bn < 512) ? g_sg : g_sc;
  #pragma unroll
  for (int mt=0;mt<2;mt++) {
    #pragma unroll
    for (int rh=0; rh<2; rh++) {
      int row = bm + wm*32 + mt*16 + g + rh*8;
      int b = row / 600;
      int qs = (b == b_lo) ? 0 : 1;
      float s = 0.f;
      #pragma unroll
      for (int nt=0; nt<8; nt++) {
        int cl = wn*64 + nt*8 + t4*2;
        s += tanhf(s_q[qs][cl]   + acc[mt][nt][rh*2+0]) * s_av[cl];
        s += tanhf(s_q[qs][cl+1] + acc[mt][nt][rh*2+1]) * s_av[cl+1];
      }
      s += __shfl_xor_sync(0xffffffffu, s, 1);
      s += __shfl_xor_sync(0xffffffffu, s, 2);
      if (t4 == 0) atomicAdd(&dst[row], s);
    }
  }
}

// ---------------- small-M GEMM, float4 cols, K-split + atomic accumulate ----------------
struct GArgs {
  const float* A0; const float* A1;
  const float* W0; const float* W1;
  const int* xidx; const float* emb;
  float* C;
  int K; int N;
};

enum { V_Z1=0, V_Z2=1, V_Q=2, V_HA=3 };

template<int VAR>
__device__ __forceinline__ float loadA(const GArgs& g, int b, int k) {
  if (VAR==V_Z1) {
    if (k < 300) return g.emb[(size_t)g.xidx[b]*300 + k];
    if (k < 812) return g.A0[b*512 + (k-300)];
    return g.A1[b*512 + (k-812)];
  }
  if (VAR==V_Z2 || VAR==V_HA) {
    if (k < 512) return g.A0[b*512+k];
    return g.A1[b*512 + (k-512)];
  }
  return g.A0[b*512+k]; // V_Q
}

template<int VAR>
__device__ __forceinline__ float4 loadW4(const GArgs& g, int k, int c) {
  if (VAR==V_Z1) return (k<812) ? *(const float4*)&g.W0[(size_t)k*2048+c]
                                : *(const float4*)&g.W1[(size_t)(k-812)*2048+c];
  if (VAR==V_Z2) return (k<512) ? *(const float4*)&g.W0[(size_t)k*2048+c]
                                : *(const float4*)&g.W1[(size_t)(k-512)*2048+c];
  if (VAR==V_Q)  return (c<512) ? *(const float4*)&g.W0[(size_t)k*512+c]
                                : *(const float4*)&g.W1[(size_t)k*512+(c-512)];
  return *(const float4*)&g.W0[(size_t)k*512+c]; // V_HA
}

#define ACC4(bi, av) \
  acc[bi].x = fmaf(av, w.x, acc[bi].x); acc[bi].y = fmaf(av, w.y, acc[bi].y); \
  acc[bi].z = fmaf(av, w.z, acc[bi].z); acc[bi].w = fmaf(av, w.w, acc[bi].w);

// grid: (N/512, ceil(K/64)); block: 128. Four columns per thread.
template<int VAR>
__global__ void gemm16_atomic(GArgs g) {
  __shared__ __align__(16) float As[64][16];
  int tid = threadIdx.x;                 // 128
  int col = blockIdx.x*512 + tid*4;
  int k0  = blockIdx.y*64;

  #pragma unroll
  for (int i=0;i<8;i++) {
    int e = tid + i*128;
    int kl = e >> 4, b = e & 15;
    int k = k0 + kl;
    As[kl][b] = (k < g.K) ? loadA<VAR>(g, b, k) : 0.f;
  }
  __syncthreads();

  float4 acc[16];
  #pragma unroll
  for (int b=0;b<16;b++) acc[b] = make_float4(0.f,0.f,0.f,0.f);

  int kmax = g.K - k0; if (kmax > 64) kmax = 64;
  #pragma unroll 2
  for (int kl=0; kl<kmax; kl++) {
    float4 w = loadW4<VAR>(g, k0+kl, col);
    const float4* ap = (const float4*)&As[kl][0];
    float4 v0 = ap[0], v1 = ap[1], v2 = ap[2], v3 = ap[3];
    ACC4(0, v0.x)  ACC4(1, v0.y)  ACC4(2, v0.z)  ACC4(3, v0.w)
    ACC4(4, v1.x)  ACC4(5, v1.y)  ACC4(6, v1.z)  ACC4(7, v1.w)
    ACC4(8, v2.x)  ACC4(9, v2.y)  ACC4(10,v2.z)  ACC4(11,v2.w)
    ACC4(12,v3.x)  ACC4(13,v3.y)  ACC4(14,v3.z)  ACC4(15,v3.w)
  }
  #pragma unroll
  for (int b=0;b<16;b++) {
    float* cp = &g.C[(size_t)b*g.N + col];
    atomicAdd(cp+0, acc[b].x); atomicAdd(cp+1, acc[b].y);
    atomicAdd(cp+2, acc[b].z); atomicAdd(cp+3, acc[b].w);
  }
}

// ---------------- logits: g_logits += ha @ Wg, float4 cols, K-split 4x128 ----------------
__global__ void gemm16_logits_split(const float* __restrict__ A, const float* __restrict__ W) {
  __shared__ __align__(16) float As[128][16];
  int tid = threadIdx.x;                 // 128
  int col = blockIdx.x*512 + tid*4;
  int k0  = blockIdx.y*128;
  #pragma unroll
  for (int i=0;i<16;i++) {
    int e = tid + i*128;
    int kl = e >> 4, b = e & 15;
    As[kl][b] = A[b*512 + k0 + kl];
  }
  __syncthreads();
  if (col >= VV) return;
  float4 acc[16];
  #pragma unroll
  for (int b=0;b<16;b++) acc[b] = make_float4(0.f,0.f,0.f,0.f);
  #pragma unroll 2
  for (int kl=0; kl<128; kl++) {
    float4 w = *(const float4*)&W[(size_t)(k0+kl)*VV + col];
    const float4* ap = (const float4*)&As[kl][0];
    float4 v0 = ap[0], v1 = ap[1], v2 = ap[2], v3 = ap[3];
    ACC4(0, v0.x)  ACC4(1, v0.y)  ACC4(2, v0.z)  ACC4(3, v0.w)
    ACC4(4, v1.x)  ACC4(5, v1.y)  ACC4(6, v1.z)  ACC4(7, v1.w)
    ACC4(8, v2.x)  ACC4(9, v2.y)  ACC4(10,v2.z)  ACC4(11,v2.w)
    ACC4(12,v3.x)  ACC4(13,v3.y)  ACC4(14,v3.z)  ACC4(15,v3.w)
  }
  #pragma unroll
  for (int b=0;b<16;b++) {
    float* cp = &g_logits[(size_t)b*VV + col];
    atomicAdd(cp+0, acc[b].x); atomicAdd(cp+1, acc[b].y);
    atomicAdd(cp+2, acc[b].z); atomicAdd(cp+3, acc[b].w);
  }
}

// ---------------- LSTM pointwise ----------------
__global__ void lstm_pw_kernel(const float* __restrict__ z, const float* __restrict__ cin,
                               float* __restrict__ hout, float* __restrict__ cout) {
  int idx = blockIdx.x*blockDim.x + threadIdx.x;
  if (idx >= BB*HH) return;
  int b = idx >> 9, j = idx & 511;
  const float* zb = z + b*2048;
  float iv = sigf(zb[j]);
  float fv = sigf(zb[512+j]);
  float gv = tanhf(zb[1024+j]);
  float ov = sigf(zb[1536+j]);
  float c = fv*cin[idx] + iv*gv;
  hout[idx] = ov*tanhf(c);
  cout[idx] = c;
}

// ---------------- softmax over T (both heads) ----------------
__global__ void softmax_kernel() {
  int b = blockIdx.x, tid = threadIdx.x;   // 256
  __shared__ float ag[TT], ac[TT];
  __shared__ float rbuf[256];
  for (int t=tid;t<TT;t+=256){ ag[t]=g_sg[b*TT+t]; ac[t]=g_sc[b*TT+t]; }
  __syncthreads();
  for (int pass=0; pass<2; pass++) {
    float* arr = pass ? ac : ag;
    float mx = -1e30f;
    for (int t=tid;t<TT;t+=256) mx = fmaxf(mx, arr[t]);
    rbuf[tid]=mx; __syncthreads();
    for (int s=128;s>0;s>>=1){ if (tid<s) rbuf[tid]=fmaxf(rbuf[tid],rbuf[tid+s]); __syncthreads(); }
    mx = rbuf[0]; __syncthreads();
    float ls=0.f;
    for (int t=tid;t<TT;t+=256){ float e=expf(arr[t]-mx); arr[t]=e; ls+=e; }
    rbuf[tid]=ls; __syncthreads();
    for (int s=128;s>0;s>>=1){ if (tid<s) rbuf[tid]+=rbuf[tid+s]; __syncthreads(); }
    float inv = 1.0f/rbuf[0]; __syncthreads();
    for (int t=tid;t<TT;t+=256) arr[t]*=inv;
    __syncthreads();
  }
  for (int t=tid;t<TT;t+=256){ g_aligng[b*TT+t]=ag[t]; g_alignc[b*TT+t]=ac[t]; }
}

// ---------------- context = align_g @ enc_outs, T-sliced + atomic ----------------
__global__ void ctx_kernel(const float* __restrict__ enc) {
  int s = blockIdx.x;            // 0..9
  int b = blockIdx.y;
  int tid = threadIdx.x;         // 512
  __shared__ float ag[60];
  if (tid < 60) ag[tid] = g_aligng[b*TT + s*60 + tid];
  __syncthreads();
  const float* eb = enc + (size_t)b*TT*HH + (size_t)(s*60)*HH + tid;
  float a0=0.f,a1=0.f,a2=0.f,a3=0.f,a4=0.f,a5=0.f;
  #pragma unroll 2
  for (int t=0;t<60;t+=6){
    a0 += ag[t]  *eb[(size_t)(t  )*HH];
    a1 += ag[t+1]*eb[(size_t)(t+1)*HH];
    a2 += ag[t+2]*eb[(size_t)(t+2)*HH];
    a3 += ag[t+3]*eb[(size_t)(t+3)*HH];
    a4 += ag[t+4]*eb[(size_t)(t+4)*HH];
    a5 += ag[t+5]*eb[(size_t)(t+5)*HH];
  }
  atomicAdd(&g_ctx[b*HH+tid], (a0+a1)+(a2+a3)+(a4+a5));
}

// ---------------- hidden_att finalize: tanh + switch ----------------
__global__ void ha_finalize_kernel(float* __restrict__ out_hidden,
                                   const float* __restrict__ Wf, const float* __restrict__ bf) {
  int b = blockIdx.x, tid = threadIdx.x;   // 512
  __shared__ float rb[512];
  float t = tanhf(g_ha[b*HH+tid]);
  out_hidden[b*HH+tid] = t;
  rb[tid] = t*Wf[tid];
  __syncthreads();
  for (int s=256;s>0;s>>=1){ if (tid<s) rb[tid]+=rb[tid+s]; __syncthreads(); }
  if (tid==0) g_switch[b] = sigf(rb[0]+bf[0]);
}

// ---------------- vocab softmax reductions, two-stage ----------------
__global__ void vred1_kernel() {
  int s = blockIdx.x, b = blockIdx.y;      // 10 x 16
  int tid = threadIdx.x;                   // 256
  __shared__ float rb[256];
  const float* lb = g_logits + (size_t)b*VV + s*2000;
  float mx = -1e30f;
  for (int i=tid;i<2000;i+=256) mx = fmaxf(mx, lb[i]);
  rb[tid]=mx; __syncthreads();
  for (int st=128;st>0;st>>=1){ if (tid<st) rb[tid]=fmaxf(rb[tid],rb[tid+st]); __syncthreads(); }
  mx = rb[0]; __syncthreads();
  float sm=0.f;
  for (int i=tid;i<2000;i+=256) sm += expf(lb[i]-mx);
  rb[tid]=sm; __syncthreads();
  for (int st=128;st>0;st>>=1){ if (tid<st) rb[tid]+=rb[tid+st]; __syncthreads(); }
  if (tid==0){ g_pm[b*10+s]=mx; g_ps[b*10+s]=rb[0]; }
}

__global__ void vred2_kernel() {
  int b = blockIdx.x, tid = threadIdx.x;   // 32
  float m = (tid<10) ? g_pm[b*10+tid] : -1e30f;
  #pragma unroll
  for (int o=16;o>0;o>>=1) m = fmaxf(m, __shfl_xor_sync(0xffffffffu, m, o));
  float s = (tid<10) ? g_ps[b*10+tid]*expf(g_pm[b*10+tid]-m) : 0.f;
  #pragma unroll
  for (int o=16;o>0;o>>=1) s += __shfl_xor_sync(0xffffffffu, s, o);
  if (tid==0){ g_vred[b*2]=m; g_vred[b*2+1]=s; }
}

// ---------------- final: copy_prob bf16 stream + mix ----------------
__global__ void final_kernel(float* __restrict__ result) {
  int b = blockIdx.y, tid = threadIdx.x;   // 256
  int v = (blockIdx.x*256 + tid)*2;
  __shared__ float ac[TT];
  for (int t=tid;t<TT;t+=256) ac[t]=g_alignc[b*TT+t];
  __syncthreads();
  if (v >= VV) return;
  const __nv_bfloat162* eb = (const __nv_bfloat162*)g_encb + ((size_t)b*TT*VV + v)/2;
  float s0x=0.f,s0y=0.f,s1x=0.f,s1y=0.f,s2x=0.f,s2y=0.f,s3x=0.f,s3y=0.f;
  for (int t=0;t<TT;t+=4){
    float2 e0 = __bfloat1622float2(eb[(size_t)(t  )*(VV/2)]);
    float2 e1 = __bfloat1622float2(eb[(size_t)(t+1)*(VV/2)]);
    float2 e2 = __bfloat1622float2(eb[(size_t)(t+2)*(VV/2)]);
    float2 e3 = __bfloat1622float2(eb[(size_t)(t+3)*(VV/2)]);
    s0x = fmaf(ac[t],  e0.x, s0x); s0y = fmaf(ac[t],  e0.y, s0y);
    s1x = fmaf(ac[t+1],e1.x, s1x); s1y = fmaf(ac[t+1],e1.y, s1y);
    s2x = fmaf(ac[t+2],e2.x, s2x); s2y = fmaf(ac[t+2],e2.y, s2y);
    s3x = fmaf(ac[t+3],e3.x, s3x); s3y = fmaf(ac[t+3],e3.y, s3y);
  }
  float copyx = (s0x+s1x)+(s2x+s3x);
  float copyy = (s0y+s1y)+(s2y+s3y);
  float sw = g_switch[b];
  float mx = g_vred[b*2], sm = g_vred[b*2+1];
  float genx = expf(g_logits[(size_t)b*VV+v]-mx)/sm;
  float geny = expf(g_logits[(size_t)b*VV+v+1]-mx)/sm;
  result[(size_t)b*VV+v]   = genx*(1.0f-sw) + copyx*sw;
  result[(size_t)b*VV+v+1] = geny*(1.0f-sw) + copyy*sw;
}

// ---------------- launch ----------------
extern "C" void kernel_launch(void* const* d_in, const int* in_sizes, int n_in,
                              void* d_out, int out_size) {
  const int*   x        = (const int*)  d_in[0];
  const float* lha      = (const float*)d_in[1];
  const float* h1       = (const float*)d_in[2];
  const float* c1       = (const float*)d_in[3];
  const float* h2       = (const float*)d_in[4];
  const float* c2       = (const float*)d_in[5];
  const float* enc_outs = (const float*)d_in[6];
  const float* enc_ins  = (const float*)d_in[7];
  const float* emb      = (const float*)d_in[8];
  const float* k1       = (const float*)d_in[9];
  const float* r1       = (const float*)d_in[10];
  const float* b1       = (const float*)d_in[11];
  const float* k2       = (const float*)d_in[12];
  const float* r2       = (const float*)d_in[13];
  const float* b2       = (const float*)d_in[14];
  const float* Wh       = (const float*)d_in[15];
  const float* bh       = (const float*)d_in[16];
  const float* Wg       = (const float*)d_in[17];
  const float* bg       = (const float*)d_in[18];
  const float* Wf       = (const float*)d_in[19];
  const float* bf       = (const float*)d_in[20];
  const float* aw1g     = (const float*)d_in[21];
  const float* aw2g     = (const float*)d_in[22];
  const float* avg      = (const float*)d_in[23];
  const float* aw1c     = (const float*)d_in[24];
  const float* aw2c     = (const float*)d_in[25];
  const float* avc      = (const float*)d_in[26];

  float* out = (float*)d_out;
  float* out_result = out;                       // 16*20000
  float* out_hidden = out + BB*VV;
  float* out_h1n    = out_hidden + BB*HH;
  float* out_c1n    = out_h1n + BB*HH;
  float* out_h2n    = out_c1n + BB*HH;
  float* out_c2n    = out_h2n + BB*HH;

  float *p_z1, *p_z2, *p_q, *p_ctx, *p_ha;
  cudaGetSymbolAddress((void**)&p_z1, g_z1);
  cudaGetSymbolAddress((void**)&p_z2, g_z2);
  cudaGetSymbolAddress((void**)&p_q, g_q);
  cudaGetSymbolAddress((void**)&p_ctx, g_ctx);
  cudaGetSymbolAddress((void**)&p_ha, g_ha);

  // side stream (low priority) + fork/join events; created fresh each call,
  // never destroyed (kernel_launch runs only a handful of times, not in the timed loop)
  int prLeast = 0, prGreatest = 0;
  cudaDeviceGetStreamPriorityRange(&prLeast, &prGreatest);
  cudaStream_t s2;
  cudaStreamCreateWithPriority(&s2, cudaStreamNonBlocking, prLeast);
  cudaEvent_t evFork, evJ1, evJ2;
  cudaEventCreateWithFlags(&evFork, cudaEventDisableTiming);
  cudaEventCreateWithFlags(&evJ1, cudaEventDisableTiming);
  cudaEventCreateWithFlags(&evJ2, cudaEventDisableTiming);

  // fork side stream from main
  cudaEventRecord(evFork, 0);
  cudaStreamWaitEvent(s2, evFork, 0);

  // side stream: bf16 conversions for mma, then the big enc_ins conversion
  convA_kernel<<<(BT*512/4 + 255)/256, 256, 0, s2>>>(enc_outs);
  convW_kernel<<<dim3(16,32), 256, 0, s2>>>(aw2g, aw2c);
  cudaEventRecord(evJ1, s2);
  convEnc_kernel<<<23438, 256, 0, s2>>>(enc_ins);
  cudaEventRecord(evJ2, s2);

  // main stream: init + LSTM chain
  init_kernel<<<(INIT_TOTAL+255)/256, 256>>>(b1, b2, bh, bg);

  GArgs az1; az1.A0=lha; az1.A1=h1; az1.W0=k1; az1.W1=r1;
  az1.xidx=x; az1.emb=emb; az1.C=p_z1; az1.K=1324; az1.N=2048;
  gemm16_atomic<V_Z1><<<dim3(4,21),128>>>(az1);
  lstm_pw_kernel<<<32,256>>>(p_z1, c1, out_h1n, out_c1n);

  GArgs az2; az2.A0=out_h1n; az2.A1=h2; az2.W0=k2; az2.W1=r2;
  az2.xidx=nullptr; az2.emb=nullptr; az2.C=p_z2; az2.K=1024; az2.N=2048;
  gemm16_atomic<V_Z2><<<dim3(4,16),128>>>(az2);
  lstm_pw_kernel<<<32,256>>>(p_z2, c2, out_h2n, out_c2n);

  GArgs aq; aq.A0=out_h2n; aq.A1=nullptr; aq.W0=aw1g; aq.W1=aw1c;
  aq.xidx=nullptr; aq.emb=nullptr; aq.C=p_q; aq.K=512; aq.N=1024;
  gemm16_atomic<V_Q><<<dim3(2,8),128>>>(aq);

  // join 1: need bf16 enc/W for mma
  cudaStreamWaitEvent(0, evJ1, 0);
  mma_attn_scores_kernel<<<dim3(75,8), 256>>>(avg, avc);

  softmax_kernel<<<BB,256>>>();
  ctx_kernel<<<dim3(10,BB),512>>>(enc_outs);

  GArgs aha; aha.A0=p_ctx; aha.A1=out_h2n; aha.W0=Wh; aha.W1=nullptr;
  aha.xidx=nullptr; aha.emb=nullptr; aha.C=p_ha; aha.K=1024; aha.N=512;
  gemm16_atomic<V_HA><<<dim3(1,16),128>>>(aha);
  ha_finalize_kernel<<<BB,512>>>(out_hidden, Wf, bf);

  gemm16_logits_split<<<dim3(40,4),128>>>(out_hidden, Wg);
  vred1_kernel<<<dim3(10,BB),256>>>();
  vred2_kernel<<<BB,32>>>();

  // join 2: need bf16 enc_ins for the copy pass
  cudaStreamWaitEvent(0, evJ2, 0);
  final_kernel<<<dim3((VV/2+255)/256, BB), 256>>>(out_result);
}

// round 9
// speedup vs baseline: 1.1647x; 1.1647x over previous
#include <cuda_runtime.h>
#include <cuda_bf16.h>
#include <math.h>
#include <stdint.h>

#define BB 16
#define TT 600
#define VV 20000
#define EE 300
#define HH 512
#define BT (BB*TT)   // 9600

// ---------------- scratch ----------------
__device__ uint32_t g_A2h[(size_t)BT*256];   // enc hi, bf16 [9600][512] packed as u32
__device__ uint32_t g_A2l[(size_t)BT*256];   // enc lo
__device__ uint32_t g_Wth[1024*256];         // W^T hi, bf16 [1024 n][512 k]
__device__ uint32_t g_Wtl[1024*256];         // W^T lo
__device__ float g_z1[BB*2048];
__device__ float g_z2[BB*2048];
__device__ float g_q[BB*1024];
__device__ float g_ha[BB*HH];
__device__ float g_sg[BB*TT];
__device__ float g_sc[BB*TT];
__device__ float g_aligng[BB*TT];
__device__ float g_alignc[BB*TT];
__device__ float g_ctx[BB*HH];
__device__ float g_logits[(size_t)BB*VV];
__device__ float g_pm[BB*10];
__device__ float g_ps[BB*10];
__device__ float g_vred[BB*2];
__device__ float g_switch[BB];

__device__ __forceinline__ float sigf(float x){ return 1.0f/(1.0f+expf(-x)); }

// ---------------- init: biases / zeros into accumulators ----------------
#define INIT_TOTAL (117504 + 320000)
__global__ void init_kernel(const float* __restrict__ b1, const float* __restrict__ b2,
                            const float* __restrict__ bh, const float* __restrict__ bg) {
  int idx = blockIdx.x*blockDim.x + threadIdx.x;
  if (idx < 32768)            g_z1[idx] = b1[idx & 2047];
  else if (idx < 65536)       g_z2[idx-32768] = b2[idx & 2047];
  else if (idx < 81920)       g_q[idx-65536] = 0.f;
  else if (idx < 90112)       g_ha[idx-81920] = bh[idx & 511];
  else if (idx < 98304)       g_ctx[idx-90112] = 0.f;
  else if (idx < 107904)      g_sg[idx-98304] = 0.f;
  else if (idx < 117504)      g_sc[idx-107904] = 0.f;
  else if (idx < INIT_TOTAL) {
    int e = idx - 117504;
    g_logits[e] = bg[e % VV];
  }
}

// ---------------- convert enc_outs -> bf16 hi/lo ----------------
__global__ void convA_kernel(const float* __restrict__ A) {
  int i4 = blockIdx.x*blockDim.x + threadIdx.x;
  if (i4 >= BT*512/4) return;
  float4 v = *(const float4*)&A[i4*4];
  __nv_bfloat16 h0 = __float2bfloat16(v.x);
  __nv_bfloat16 h1 = __float2bfloat16(v.y);
  __nv_bfloat16 h2 = __float2bfloat16(v.z);
  __nv_bfloat16 h3 = __float2bfloat16(v.w);
  __nv_bfloat16 l0 = __float2bfloat16(v.x - __bfloat162float(h0));
  __nv_bfloat16 l1 = __float2bfloat16(v.y - __bfloat162float(h1));
  __nv_bfloat16 l2 = __float2bfloat16(v.z - __bfloat162float(h2));
  __nv_bfloat16 l3 = __float2bfloat16(v.w - __bfloat162float(h3));
  __nv_bfloat162* ph = (__nv_bfloat162*)g_A2h;
  __nv_bfloat162* pl = (__nv_bfloat162*)g_A2l;
  ph[i4*2]   = __nv_bfloat162(h0,h1);
  ph[i4*2+1] = __nv_bfloat162(h2,h3);
  pl[i4*2]   = __nv_bfloat162(l0,l1);
  pl[i4*2+1] = __nv_bfloat162(l2,l3);
}

// ---------------- transpose + convert W -> Wt bf16 hi/lo ----------------
__global__ void convW_kernel(const float* __restrict__ Wg, const float* __restrict__ Wc) {
  __shared__ float tile[32][33];
  int k0 = blockIdx.x*32;
  int n0 = blockIdx.y*32;
  const float* W = (n0 < 512) ? Wg : Wc;
  int nn0 = n0 & 511;
  int tx = threadIdx.x & 31, ty = threadIdx.x >> 5;
  #pragma unroll
  for (int i=0;i<4;i++) {
    int k = k0 + ty + i*8;
    tile[ty+i*8][tx] = W[(size_t)k*512 + nn0 + tx];
  }
  __syncthreads();
  __nv_bfloat16* WH = (__nv_bfloat16*)g_Wth;
  __nv_bfloat16* WL = (__nv_bfloat16*)g_Wtl;
  #pragma unroll
  for (int i=0;i<4;i++) {
    int n = n0 + ty + i*8;
    float x = tile[tx][ty+i*8];
    __nv_bfloat16 h = __float2bfloat16(x);
    WH[(size_t)n*512 + k0 + tx] = h;
    WL[(size_t)n*512 + k0 + tx] = __float2bfloat16(x - __bfloat162float(h));
  }
}

// ---------------- mma helpers ----------------
__device__ __forceinline__ void mma16816(float* c, const uint32_t* a, const uint32_t* b) {
  asm volatile(
    "mma.sync.aligned.m16n8k16.row.col.f32.bf16.bf16.f32 "
    "{%0,%1,%2,%3}, {%4,%5,%6,%7}, {%8,%9}, {%0,%1,%2,%3};"
    : "+f"(c[0]), "+f"(c[1]), "+f"(c[2]), "+f"(c[3])
    : "r"(a[0]), "r"(a[1]), "r"(a[2]), "r"(a[3]), "r"(b[0]), "r"(b[1]));
}

__device__ __forceinline__ void ldm_x4(uint32_t* r, uint32_t addr) {
  asm volatile("ldmatrix.sync.aligned.m8n8.x4.shared.b16 {%0,%1,%2,%3}, [%4];"
    : "=r"(r[0]), "=r"(r[1]), "=r"(r[2]), "=r"(r[3]) : "r"(addr));
}

// ---------------- fused: P = enc @ [aw2g|aw2c]; scores += tanh(q+P)*av ----------------
__global__ void __launch_bounds__(256, 2) mma_attn_scores_kernel(
    const float* __restrict__ avg, const float* __restrict__ avc) {
  __shared__ uint32_t sAh[128*20];
  __shared__ uint32_t sAl[128*20];
  __shared__ uint32_t sBh[128*20];
  __shared__ uint32_t sBl[128*20];
  __shared__ float s_av[128];
  __shared__ float s_q[2][128];

  int tid = threadIdx.x;
  int bm = blockIdx.x * 128;     // 75
  int bn = blockIdx.y * 128;     // 8
  int wid = tid >> 5, lane = tid & 31;
  int wm = wid >> 1, wn = wid & 1;
  int g = lane >> 2, t4 = lane & 3;

  int b_lo = bm / 600;
  int b_hi = (bm + 127) / 600;
  if (tid < 128) {
    const float* av = (bn < 512) ? avg : avc;
    s_av[tid] = av[(bn & 511) + tid];
    s_q[0][tid] = g_q[b_lo*1024 + bn + tid];
    s_q[1][tid] = g_q[b_hi*1024 + bn + tid];
  }

  uint32_t baseAh = (uint32_t)__cvta_generic_to_shared(sAh);
  uint32_t baseAl = (uint32_t)__cvta_generic_to_shared(sAl);
  uint32_t baseBh = (uint32_t)__cvta_generic_to_shared(sBh);
  uint32_t baseBl = (uint32_t)__cvta_generic_to_shared(sBl);
  uint32_t aoff = ((uint32_t)((wm*32 + (lane & 15))*20 + (lane >> 4)*4)) * 4;
  uint32_t aAh0 = baseAh + aoff, aAl0 = baseAl + aoff;
  uint32_t boff = ((uint32_t)((wn*64 + (lane & 7) + ((lane >> 4) << 3))*20 + ((lane >> 3) & 1)*4)) * 4;
  uint32_t bBh0 = baseBh + boff, bBl0 = baseBl + boff;

  float acc[2][8][4];
  #pragma unroll
  for (int mt=0;mt<2;mt++)
    #pragma unroll
    for (int nt=0;nt<8;nt++)
      #pragma unroll
      for (int r=0;r<4;r++) acc[mt][nt][r]=0.f;

  for (int kc=0; kc<512; kc+=32) {
    #pragma unroll
    for (int i=0;i<8;i++) {
      int e = tid + i*256;
      int row = e >> 4, kw = e & 15;
      size_t ga = (size_t)(bm+row)*256 + (kc>>1) + kw;
      size_t gb = (size_t)(bn+row)*256 + (kc>>1) + kw;
      int ss = row*20 + kw;
      sAh[ss] = g_A2h[ga];
      sAl[ss] = g_A2l[ga];
      sBh[ss] = g_Wth[gb];
      sBl[ss] = g_Wtl[gb];
    }
    __syncthreads();

    #pragma unroll
    for (int ks=0; ks<2; ks++) {
      uint32_t kb = ks*32;
      uint32_t ah[2][4], al[2][4];
      ldm_x4(ah[0], aAh0 + kb);
      ldm_x4(ah[1], aAh0 + 1280 + kb);
      ldm_x4(al[0], aAl0 + kb);
      ldm_x4(al[1], aAl0 + 1280 + kb);
      #pragma unroll
      for (int ntp=0; ntp<4; ntp++) {
        uint32_t bh4[4], bl4[4];
        ldm_x4(bh4, bBh0 + (uint32_t)ntp*1280 + kb);
        ldm_x4(bl4, bBl0 + (uint32_t)ntp*1280 + kb);
        int n0 = ntp*2, n1 = ntp*2+1;
        #pragma unroll
        for (int mt=0;mt<2;mt++) {
          mma16816(acc[mt][n0], ah[mt], bh4+0);
          mma16816(acc[mt][n0], ah[mt], bl4+0);
          mma16816(acc[mt][n0], al[mt], bh4+0);
          mma16816(acc[mt][n1], ah[mt], bh4+2);
          mma16816(acc[mt][n1], ah[mt], bl4+2);
          mma16816(acc[mt][n1], al[mt], bh4+2);
        }
      }
    }
    __syncthreads();
  }

  float* dst = (bn < 512) ? g_sg : g_sc;
  #pragma unroll
  for (int mt=0;mt<2;mt++) {
    #pragma unroll
    for (int rh=0; rh<2; rh++) {
      int row = bm + wm*32 + mt*16 + g + rh*8;
      int b = row / 600;
      int qs = (b == b_lo) ? 0 : 1;
      float s = 0.f;
      #pragma unroll
      for (int nt=0; nt<8; nt++) {
        int cl = wn*64 + nt*8 + t4*2;
        s += tanhf(s_q[qs][cl]   + acc[mt][nt][rh*2+0]) * s_av[cl];
        s += tanhf(s_q[qs][cl+1] + acc[mt][nt][rh*2+1]) * s_av[cl+1];
      }
      s += __shfl_xor_sync(0xffffffffu, s, 1);
      s += __shfl_xor_sync(0xffffffffu, s, 2);
      if (t4 == 0) atomicAdd(&dst[row], s);
    }
  }
}

// ---------------- small-M GEMM, float4 cols, K-split + atomic accumulate ----------------
struct GArgs {
  const float* A0; const float* A1;
  const float* W0; const float* W1;
  const int* xidx; const float* emb;
  float* C;
  int K; int N;
};

enum { V_Z1=0, V_Z2=1, V_Q=2, V_HA=3 };

template<int VAR>
__device__ __forceinline__ float loadA(const GArgs& g, int b, int k) {
  if (VAR==V_Z1) {
    if (k < 300) return g.emb[(size_t)g.xidx[b]*300 + k];
    if (k < 812) return g.A0[b*512 + (k-300)];
    return g.A1[b*512 + (k-812)];
  }
  if (VAR==V_Z2 || VAR==V_HA) {
    if (k < 512) return g.A0[b*512+k];
    return g.A1[b*512 + (k-512)];
  }
  return g.A0[b*512+k]; // V_Q
}

template<int VAR>
__device__ __forceinline__ float4 loadW4(const GArgs& g, int k, int c) {
  if (VAR==V_Z1) return (k<812) ? *(const float4*)&g.W0[(size_t)k*2048+c]
                                : *(const float4*)&g.W1[(size_t)(k-812)*2048+c];
  if (VAR==V_Z2) return (k<512) ? *(const float4*)&g.W0[(size_t)k*2048+c]
                                : *(const float4*)&g.W1[(size_t)(k-512)*2048+c];
  if (VAR==V_Q)  return (c<512) ? *(const float4*)&g.W0[(size_t)k*512+c]
                                : *(const float4*)&g.W1[(size_t)k*512+(c-512)];
  return *(const float4*)&g.W0[(size_t)k*512+c]; // V_HA
}

#define ACC4(bi, av) \
  acc[bi].x = fmaf(av, w.x, acc[bi].x); acc[bi].y = fmaf(av, w.y, acc[bi].y); \
  acc[bi].z = fmaf(av, w.z, acc[bi].z); acc[bi].w = fmaf(av, w.w, acc[bi].w);

// grid: (N/512, ceil(K/64)); block: 128. Four columns per thread.
template<int VAR>
__global__ void gemm16_atomic(GArgs g) {
  __shared__ __align__(16) float As[64][16];
  int tid = threadIdx.x;                 // 128
  int col = blockIdx.x*512 + tid*4;
  int k0  = blockIdx.y*64;

  #pragma unroll
  for (int i=0;i<8;i++) {
    int e = tid + i*128;
    int kl = e >> 4, b = e & 15;
    int k = k0 + kl;
    As[kl][b] = (k < g.K) ? loadA<VAR>(g, b, k) : 0.f;
  }
  __syncthreads();

  float4 acc[16];
  #pragma unroll
  for (int b=0;b<16;b++) acc[b] = make_float4(0.f,0.f,0.f,0.f);

  int kmax = g.K - k0; if (kmax > 64) kmax = 64;
  #pragma unroll 2
  for (int kl=0; kl<kmax; kl++) {
    float4 w = loadW4<VAR>(g, k0+kl, col);
    const float4* ap = (const float4*)&As[kl][0];
    float4 v0 = ap[0], v1 = ap[1], v2 = ap[2], v3 = ap[3];
    ACC4(0, v0.x)  ACC4(1, v0.y)  ACC4(2, v0.z)  ACC4(3, v0.w)
    ACC4(4, v1.x)  ACC4(5, v1.y)  ACC4(6, v1.z)  ACC4(7, v1.w)
    ACC4(8, v2.x)  ACC4(9, v2.y)  ACC4(10,v2.z)  ACC4(11,v2.w)
    ACC4(12,v3.x)  ACC4(13,v3.y)  ACC4(14,v3.z)  ACC4(15,v3.w)
  }
  #pragma unroll
  for (int b=0;b<16;b++) {
    float* cp = &g.C[(size_t)b*g.N + col];
    atomicAdd(cp+0, acc[b].x); atomicAdd(cp+1, acc[b].y);
    atomicAdd(cp+2, acc[b].z); atomicAdd(cp+3, acc[b].w);
  }
}

// ---------------- logits: g_logits += ha @ Wg, float4 cols, K-split 4x128 ----------------
__global__ void gemm16_logits_split(const float* __restrict__ A, const float* __restrict__ W) {
  __shared__ __align__(16) float As[128][16];
  int tid = threadIdx.x;                 // 128
  int col = blockIdx.x*512 + tid*4;
  int k0  = blockIdx.y*128;
  #pragma unroll
  for (int i=0;i<16;i++) {
    int e = tid + i*128;
    int kl = e >> 4, b = e & 15;
    As[kl][b] = A[b*512 + k0 + kl];
  }
  __syncthreads();
  if (col >= VV) return;
  float4 acc[16];
  #pragma unroll
  for (int b=0;b<16;b++) acc[b] = make_float4(0.f,0.f,0.f,0.f);
  #pragma unroll 2
  for (int kl=0; kl<128; kl++) {
    float4 w = *(const float4*)&W[(size_t)(k0+kl)*VV + col];
    const float4* ap = (const float4*)&As[kl][0];
    float4 v0 = ap[0], v1 = ap[1], v2 = ap[2], v3 = ap[3];
    ACC4(0, v0.x)  ACC4(1, v0.y)  ACC4(2, v0.z)  ACC4(3, v0.w)
    ACC4(4, v1.x)  ACC4(5, v1.y)  ACC4(6, v1.z)  ACC4(7, v1.w)
    ACC4(8, v2.x)  ACC4(9, v2.y)  ACC4(10,v2.z)  ACC4(11,v2.w)
    ACC4(12,v3.x)  ACC4(13,v3.y)  ACC4(14,v3.z)  ACC4(15,v3.w)
  }
  #pragma unroll
  for (int b=0;b<16;b++) {
    float* cp = &g_logits[(size_t)b*VV + col];
    atomicAdd(cp+0, acc[b].x); atomicAdd(cp+1, acc[b].y);
    atomicAdd(cp+2, acc[b].z); atomicAdd(cp+3, acc[b].w);
  }
}

// ---------------- LSTM pointwise ----------------
__global__ void lstm_pw_kernel(const float* __restrict__ z, const float* __restrict__ cin,
                               float* __restrict__ hout, float* __restrict__ cout) {
  int idx = blockIdx.x*blockDim.x + threadIdx.x;
  if (idx >= BB*HH) return;
  int b = idx >> 9, j = idx & 511;
  const float* zb = z + b*2048;
  float iv = sigf(zb[j]);
  float fv = sigf(zb[512+j]);
  float gv = tanhf(zb[1024+j]);
  float ov = sigf(zb[1536+j]);
  float c = fv*cin[idx] + iv*gv;
  hout[idx] = ov*tanhf(c);
  cout[idx] = c;
}

// ---------------- softmax over T (both heads) ----------------
__global__ void softmax_kernel() {
  int b = blockIdx.x, tid = threadIdx.x;   // 256
  __shared__ float ag[TT], ac[TT];
  __shared__ float rbuf[256];
  for (int t=tid;t<TT;t+=256){ ag[t]=g_sg[b*TT+t]; ac[t]=g_sc[b*TT+t]; }
  __syncthreads();
  for (int pass=0; pass<2; pass++) {
    float* arr = pass ? ac : ag;
    float mx = -1e30f;
    for (int t=tid;t<TT;t+=256) mx = fmaxf(mx, arr[t]);
    rbuf[tid]=mx; __syncthreads();
    for (int s=128;s>0;s>>=1){ if (tid<s) rbuf[tid]=fmaxf(rbuf[tid],rbuf[tid+s]); __syncthreads(); }
    mx = rbuf[0]; __syncthreads();
    float ls=0.f;
    for (int t=tid;t<TT;t+=256){ float e=expf(arr[t]-mx); arr[t]=e; ls+=e; }
    rbuf[tid]=ls; __syncthreads();
    for (int s=128;s>0;s>>=1){ if (tid<s) rbuf[tid]+=rbuf[tid+s]; __syncthreads(); }
    float inv = 1.0f/rbuf[0]; __syncthreads();
    for (int t=tid;t<TT;t+=256) arr[t]*=inv;
    __syncthreads();
  }
  for (int t=tid;t<TT;t+=256){ g_aligng[b*TT+t]=ag[t]; g_alignc[b*TT+t]=ac[t]; }
}

// ---------------- context = align_g @ enc_outs, T-sliced + atomic ----------------
__global__ void ctx_kernel(const float* __restrict__ enc) {
  int s = blockIdx.x;            // 0..9
  int b = blockIdx.y;
  int tid = threadIdx.x;         // 512
  __shared__ float ag[60];
  if (tid < 60) ag[tid] = g_aligng[b*TT + s*60 + tid];
  __syncthreads();
  const float* eb = enc + (size_t)b*TT*HH + (size_t)(s*60)*HH + tid;
  float a0=0.f,a1=0.f,a2=0.f,a3=0.f,a4=0.f,a5=0.f;
  #pragma unroll 2
  for (int t=0;t<60;t+=6){
    a0 += ag[t]  *eb[(size_t)(t  )*HH];
    a1 += ag[t+1]*eb[(size_t)(t+1)*HH];
    a2 += ag[t+2]*eb[(size_t)(t+2)*HH];
    a3 += ag[t+3]*eb[(size_t)(t+3)*HH];
    a4 += ag[t+4]*eb[(size_t)(t+4)*HH];
    a5 += ag[t+5]*eb[(size_t)(t+5)*HH];
  }
  atomicAdd(&g_ctx[b*HH+tid], (a0+a1)+(a2+a3)+(a4+a5));
}

// ---------------- hidden_att finalize: tanh + switch ----------------
__global__ void ha_finalize_kernel(float* __restrict__ out_hidden,
                                   const float* __restrict__ Wf, const float* __restrict__ bf) {
  int b = blockIdx.x, tid = threadIdx.x;   // 512
  __shared__ float rb[512];
  float t = tanhf(g_ha[b*HH+tid]);
  out_hidden[b*HH+tid] = t;
  rb[tid] = t*Wf[tid];
  __syncthreads();
  for (int s=256;s>0;s>>=1){ if (tid<s) rb[tid]+=rb[tid+s]; __syncthreads(); }
  if (tid==0) g_switch[b] = sigf(rb[0]+bf[0]);
}

// ---------------- vocab softmax reductions, two-stage ----------------
__global__ void vred1_kernel() {
  int s = blockIdx.x, b = blockIdx.y;      // 10 x 16
  int tid = threadIdx.x;                   // 256
  __shared__ float rb[256];
  const float* lb = g_logits + (size_t)b*VV + s*2000;
  float mx = -1e30f;
  for (int i=tid;i<2000;i+=256) mx = fmaxf(mx, lb[i]);
  rb[tid]=mx; __syncthreads();
  for (int st=128;st>0;st>>=1){ if (tid<st) rb[tid]=fmaxf(rb[tid],rb[tid+st]); __syncthreads(); }
  mx = rb[0]; __syncthreads();
  float sm=0.f;
  for (int i=tid;i<2000;i+=256) sm += expf(lb[i]-mx);
  rb[tid]=sm; __syncthreads();
  for (int st=128;st>0;st>>=1){ if (tid<st) rb[tid]+=rb[tid+st]; __syncthreads(); }
  if (tid==0){ g_pm[b*10+s]=mx; g_ps[b*10+s]=rb[0]; }
}

__global__ void vred2_kernel() {
  int b = blockIdx.x, tid = threadIdx.x;   // 32
  float m = (tid<10) ? g_pm[b*10+tid] : -1e30f;
  #pragma unroll
  for (int o=16;o>0;o>>=1) m = fmaxf(m, __shfl_xor_sync(0xffffffffu, m, o));
  float s = (tid<10) ? g_ps[b*10+tid]*expf(g_pm[b*10+tid]-m) : 0.f;
  #pragma unroll
  for (int o=16;o>0;o>>=1) s += __shfl_xor_sync(0xffffffffu, s, o);
  if (tid==0){ g_vred[b*2]=m; g_vred[b*2+1]=s; }
}

// ---------------- final: copy_prob fp32 stream + mix ----------------
__global__ void final_kernel(const float* __restrict__ enc_ins, float* __restrict__ result) {
  int b = blockIdx.y, tid = threadIdx.x;   // 512
  int v = blockIdx.x*512 + tid;
  __shared__ float ac[TT];
  for (int t=tid;t<TT;t+=512) ac[t]=g_alignc[b*TT+t];
  __syncthreads();
  if (v >= VV) return;
  const float* eb = enc_ins + (size_t)b*TT*VV + v;
  float a0=0.f,a1=0.f,a2=0.f,a3=0.f,a4=0.f,a5=0.f,a6=0.f,a7=0.f;
  for (int t=0;t<TT;t+=8){
    a0 += ac[t]  * eb[(size_t)(t  )*VV];
    a1 += ac[t+1]* eb[(size_t)(t+1)*VV];
    a2 += ac[t+2]* eb[(size_t)(t+2)*VV];
    a3 += ac[t+3]* eb[(size_t)(t+3)*VV];
    a4 += ac[t+4]* eb[(size_t)(t+4)*VV];
    a5 += ac[t+5]* eb[(size_t)(t+5)*VV];
    a6 += ac[t+6]* eb[(size_t)(t+6)*VV];
    a7 += ac[t+7]* eb[(size_t)(t+7)*VV];
  }
  float copy = ((a0+a1)+(a2+a3))+((a4+a5)+(a6+a7));
  float sw = g_switch[b];
  float mx = g_vred[b*2], sm = g_vred[b*2+1];
  float gen = expf(g_logits[(size_t)b*VV+v]-mx)/sm;
  result[(size_t)b*VV+v] = gen*(1.0f-sw) + copy*sw;
}

// ---------------- launch ----------------
extern "C" void kernel_launch(void* const* d_in, const int* in_sizes, int n_in,
                              void* d_out, int out_size) {
  const int*   x        = (const int*)  d_in[0];
  const float* lha      = (const float*)d_in[1];
  const float* h1       = (const float*)d_in[2];
  const float* c1       = (const float*)d_in[3];
  const float* h2       = (const float*)d_in[4];
  const float* c2       = (const float*)d_in[5];
  const float* enc_outs = (const float*)d_in[6];
  const float* enc_ins  = (const float*)d_in[7];
  const float* emb      = (const float*)d_in[8];
  const float* k1       = (const float*)d_in[9];
  const float* r1       = (const float*)d_in[10];
  const float* b1       = (const float*)d_in[11];
  const float* k2       = (const float*)d_in[12];
  const float* r2       = (const float*)d_in[13];
  const float* b2       = (const float*)d_in[14];
  const float* Wh       = (const float*)d_in[15];
  const float* bh       = (const float*)d_in[16];
  const float* Wg       = (const float*)d_in[17];
  const float* bg       = (const float*)d_in[18];
  const float* Wf       = (const float*)d_in[19];
  const float* bf       = (const float*)d_in[20];
  const float* aw1g     = (const float*)d_in[21];
  const float* aw2g     = (const float*)d_in[22];
  const float* avg      = (const float*)d_in[23];
  const float* aw1c     = (const float*)d_in[24];
  const float* aw2c     = (const float*)d_in[25];
  const float* avc      = (const float*)d_in[26];

  float* out = (float*)d_out;
  float* out_result = out;                       // 16*20000
  float* out_hidden = out + BB*VV;
  float* out_h1n    = out_hidden + BB*HH;
  float* out_c1n    = out_h1n + BB*HH;
  float* out_h2n    = out_c1n + BB*HH;
  float* out_c2n    = out_h2n + BB*HH;

  float *p_z1, *p_z2, *p_q, *p_ctx, *p_ha;
  cudaGetSymbolAddress((void**)&p_z1, g_z1);
  cudaGetSymbolAddress((void**)&p_z2, g_z2);
  cudaGetSymbolAddress((void**)&p_q, g_q);
  cudaGetSymbolAddress((void**)&p_ctx, g_ctx);
  cudaGetSymbolAddress((void**)&p_ha, g_ha);

  // side stream for the bf16 prep of the attention GEMM (overlaps LSTM chain)
  cudaStream_t s2;
  cudaStreamCreateWithFlags(&s2, cudaStreamNonBlocking);
  cudaEvent_t evFork, evJ1;
  cudaEventCreateWithFlags(&evFork, cudaEventDisableTiming);
  cudaEventCreateWithFlags(&evJ1, cudaEventDisableTiming);

  cudaEventRecord(evFork, 0);
  cudaStreamWaitEvent(s2, evFork, 0);

  convA_kernel<<<(BT*512/4 + 255)/256, 256, 0, s2>>>(enc_outs);
  convW_kernel<<<dim3(16,32), 256, 0, s2>>>(aw2g, aw2c);
  cudaEventRecord(evJ1, s2);

  // main stream: init + LSTM chain
  init_kernel<<<(INIT_TOTAL+255)/256, 256>>>(b1, b2, bh, bg);

  GArgs az1; az1.A0=lha; az1.A1=h1; az1.W0=k1; az1.W1=r1;
  az1.xidx=x; az1.emb=emb; az1.C=p_z1; az1.K=1324; az1.N=2048;
  gemm16_atomic<V_Z1><<<dim3(4,21),128>>>(az1);
  lstm_pw_kernel<<<32,256>>>(p_z1, c1, out_h1n, out_c1n);

  GArgs az2; az2.A0=out_h1n; az2.A1=h2; az2.W0=k2; az2.W1=r2;
  az2.xidx=nullptr; az2.emb=nullptr; az2.C=p_z2; az2.K=1024; az2.N=2048;
  gemm16_atomic<V_Z2><<<dim3(4,16),128>>>(az2);
  lstm_pw_kernel<<<32,256>>>(p_z2, c2, out_h2n, out_c2n);

  GArgs aq; aq.A0=out_h2n; aq.A1=nullptr; aq.W0=aw1g; aq.W1=aw1c;
  aq.xidx=nullptr; aq.emb=nullptr; aq.C=p_q; aq.K=512; aq.N=1024;
  gemm16_atomic<V_Q><<<dim3(2,8),128>>>(aq);

  // join: need bf16 enc/W for mma
  cudaStreamWaitEvent(0, evJ1, 0);
  mma_attn_scores_kernel<<<dim3(75,8), 256>>>(avg, avc);

  softmax_kernel<<<BB,256>>>();
  ctx_kernel<<<dim3(10,BB),512>>>(enc_outs);

  GArgs aha; aha.A0=p_ctx; aha.A1=out_h2n; aha.W0=Wh; aha.W1=nullptr;
  aha.xidx=nullptr; aha.emb=nullptr; aha.C=p_ha; aha.K=1024; aha.N=512;
  gemm16_atomic<V_HA><<<dim3(1,16),128>>>(aha);
  ha_finalize_kernel<<<BB,512>>>(out_hidden, Wf, bf);

  gemm16_logits_split<<<dim3(40,4),128>>>(out_hidden, Wg);
  vred1_kernel<<<dim3(10,BB),256>>>();
  vred2_kernel<<<BB,32>>>();

  final_kernel<<<dim3((VV+511)/512, BB), 512>>>(enc_ins, out_result);
}

// round 10
// speedup vs baseline: 1.4007x; 1.2026x over previous
#include <cuda_runtime.h>
#include <cuda_bf16.h>
#include <math.h>
#include <stdint.h>

#define BB 16
#define TT 600
#define VV 20000
#define EE 300
#define HH 512
#define BT (BB*TT)   // 9600

// ---------------- scratch ----------------
__device__ uint32_t g_A2h[(size_t)BT*256];   // enc hi, bf16 [9600][512] packed as u32
__device__ uint32_t g_A2l[(size_t)BT*256];   // enc lo
__device__ uint32_t g_Wth[1024*256];         // W^T hi, bf16 [1024 n][512 k]
__device__ uint32_t g_Wtl[1024*256];         // W^T lo
__device__ float g_z1[BB*2048];
__device__ float g_z2[BB*2048];
__device__ float g_q[BB*1024];
__device__ float g_ha[BB*HH];
__device__ float g_sg[BB*TT];
__device__ float g_sc[BB*TT];
__device__ float g_aligng[BB*TT];
__device__ float g_alignc[BB*TT];
__device__ float g_ctx[BB*HH];
__device__ float g_logits[(size_t)BB*VV];
__device__ float g_pm[BB*10];
__device__ float g_ps[BB*10];
__device__ float g_vred[BB*2];
__device__ float g_switch[BB];

__device__ __forceinline__ float sigf(float x){ return 1.0f/(1.0f+expf(-x)); }

__device__ __forceinline__ float tanh_fast(float x){
  float y;
  asm("tanh.approx.f32 %0, %1;" : "=f"(y) : "f"(x));
  return y;
}

// ---------------- init: biases / zeros into accumulators ----------------
#define INIT_TOTAL (117504 + 320000)
__global__ void init_kernel(const float* __restrict__ b1, const float* __restrict__ b2,
                            const float* __restrict__ bh, const float* __restrict__ bg) {
  int idx = blockIdx.x*blockDim.x + threadIdx.x;
  if (idx < 32768)            g_z1[idx] = b1[idx & 2047];
  else if (idx < 65536)       g_z2[idx-32768] = b2[idx & 2047];
  else if (idx < 81920)       g_q[idx-65536] = 0.f;
  else if (idx < 90112)       g_ha[idx-81920] = bh[idx & 511];
  else if (idx < 98304)       g_ctx[idx-90112] = 0.f;
  else if (idx < 107904)      g_sg[idx-98304] = 0.f;
  else if (idx < 117504)      g_sc[idx-107904] = 0.f;
  else if (idx < INIT_TOTAL) {
    int e = idx - 117504;
    g_logits[e] = bg[e % VV];
  }
}

// ---------------- convert enc_outs -> bf16 hi/lo ----------------
__global__ void convA_kernel(const float* __restrict__ A) {
  int i4 = blockIdx.x*blockDim.x + threadIdx.x;
  if (i4 >= BT*512/4) return;
  float4 v = *(const float4*)&A[i4*4];
  __nv_bfloat16 h0 = __float2bfloat16(v.x);
  __nv_bfloat16 h1 = __float2bfloat16(v.y);
  __nv_bfloat16 h2 = __float2bfloat16(v.z);
  __nv_bfloat16 h3 = __float2bfloat16(v.w);
  __nv_bfloat16 l0 = __float2bfloat16(v.x - __bfloat162float(h0));
  __nv_bfloat16 l1 = __float2bfloat16(v.y - __bfloat162float(h1));
  __nv_bfloat16 l2 = __float2bfloat16(v.z - __bfloat162float(h2));
  __nv_bfloat16 l3 = __float2bfloat16(v.w - __bfloat162float(h3));
  __nv_bfloat162* ph = (__nv_bfloat162*)g_A2h;
  __nv_bfloat162* pl = (__nv_bfloat162*)g_A2l;
  ph[i4*2]   = __nv_bfloat162(h0,h1);
  ph[i4*2+1] = __nv_bfloat162(h2,h3);
  pl[i4*2]   = __nv_bfloat162(l0,l1);
  pl[i4*2+1] = __nv_bfloat162(l2,l3);
}

// ---------------- transpose + convert W -> Wt bf16 hi/lo ----------------
__global__ void convW_kernel(const float* __restrict__ Wg, const float* __restrict__ Wc) {
  __shared__ float tile[32][33];
  int k0 = blockIdx.x*32;
  int n0 = blockIdx.y*32;
  const float* W = (n0 < 512) ? Wg : Wc;
  int nn0 = n0 & 511;
  int tx = threadIdx.x & 31, ty = threadIdx.x >> 5;
  #pragma unroll
  for (int i=0;i<4;i++) {
    int k = k0 + ty + i*8;
    tile[ty+i*8][tx] = W[(size_t)k*512 + nn0 + tx];
  }
  __syncthreads();
  __nv_bfloat16* WH = (__nv_bfloat16*)g_Wth;
  __nv_bfloat16* WL = (__nv_bfloat16*)g_Wtl;
  #pragma unroll
  for (int i=0;i<4;i++) {
    int n = n0 + ty + i*8;
    float x = tile[tx][ty+i*8];
    __nv_bfloat16 h = __float2bfloat16(x);
    WH[(size_t)n*512 + k0 + tx] = h;
    WL[(size_t)n*512 + k0 + tx] = __float2bfloat16(x - __bfloat162float(h));
  }
}

// ---------------- mma helpers ----------------
__device__ __forceinline__ void mma16816(float* c, const uint32_t* a, const uint32_t* b) {
  asm volatile(
    "mma.sync.aligned.m16n8k16.row.col.f32.bf16.bf16.f32 "
    "{%0,%1,%2,%3}, {%4,%5,%6,%7}, {%8,%9}, {%0,%1,%2,%3};"
    : "+f"(c[0]), "+f"(c[1]), "+f"(c[2]), "+f"(c[3])
    : "r"(a[0]), "r"(a[1]), "r"(a[2]), "r"(a[3]), "r"(b[0]), "r"(b[1]));
}

__device__ __forceinline__ void ldm_x4(uint32_t* r, uint32_t addr) {
  asm volatile("ldmatrix.sync.aligned.m8n8.x4.shared.b16 {%0,%1,%2,%3}, [%4];"
    : "=r"(r[0]), "=r"(r[1]), "=r"(r[2]), "=r"(r[3]) : "r"(addr));
}

// ---------------- fused: P = enc @ [aw2g|aw2c]; scores += tanh(q+P)*av ----------------
__global__ void __launch_bounds__(256, 2) mma_attn_scores_kernel(
    const float* __restrict__ avg, const float* __restrict__ avc) {
  __shared__ uint32_t sAh[128*20];
  __shared__ uint32_t sAl[128*20];
  __shared__ uint32_t sBh[128*20];
  __shared__ uint32_t sBl[128*20];
  __shared__ float s_av[128];
  __shared__ float s_q[2][128];

  int tid = threadIdx.x;
  int bm = blockIdx.x * 128;     // 75
  int bn = blockIdx.y * 128;     // 8
  int wid = tid >> 5, lane = tid & 31;
  int wm = wid >> 1, wn = wid & 1;
  int g = lane >> 2, t4 = lane & 3;

  int b_lo = bm / 600;
  int b_hi = (bm + 127) / 600;
  if (tid < 128) {
    const float* av = (bn < 512) ? avg : avc;
    s_av[tid] = av[(bn & 511) + tid];
    s_q[0][tid] = g_q[b_lo*1024 + bn + tid];
    s_q[1][tid] = g_q[b_hi*1024 + bn + tid];
  }

  uint32_t baseAh = (uint32_t)__cvta_generic_to_shared(sAh);
  uint32_t baseAl = (uint32_t)__cvta_generic_to_shared(sAl);
  uint32_t baseBh = (uint32_t)__cvta_generic_to_shared(sBh);
  uint32_t baseBl = (uint32_t)__cvta_generic_to_shared(sBl);
  uint32_t aoff = ((uint32_t)((wm*32 + (lane & 15))*20 + (lane >> 4)*4)) * 4;
  uint32_t aAh0 = baseAh + aoff, aAl0 = baseAl + aoff;
  uint32_t boff = ((uint32_t)((wn*64 + (lane & 7) + ((lane >> 4) << 3))*20 + ((lane >> 3) & 1)*4)) * 4;
  uint32_t bBh0 = baseBh + boff, bBl0 = baseBl + boff;

  float acc[2][8][4];
  #pragma unroll
  for (int mt=0;mt<2;mt++)
    #pragma unroll
    for (int nt=0;nt<8;nt++)
      #pragma unroll
      for (int r=0;r<4;r++) acc[mt][nt][r]=0.f;

  for (int kc=0; kc<512; kc+=32) {
    #pragma unroll
    for (int i=0;i<8;i++) {
      int e = tid + i*256;
      int row = e >> 4, kw = e & 15;
      size_t ga = (size_t)(bm+row)*256 + (kc>>1) + kw;
      size_t gb = (size_t)(bn+row)*256 + (kc>>1) + kw;
      int ss = row*20 + kw;
      sAh[ss] = g_A2h[ga];
      sAl[ss] = g_A2l[ga];
      sBh[ss] = g_Wth[gb];
      sBl[ss] = g_Wtl[gb];
    }
    __syncthreads();

    #pragma unroll
    for (int ks=0; ks<2; ks++) {
      uint32_t kb = ks*32;
      uint32_t ah[2][4], al[2][4];
      ldm_x4(ah[0], aAh0 + kb);
      ldm_x4(ah[1], aAh0 + 1280 + kb);
      ldm_x4(al[0], aAl0 + kb);
      ldm_x4(al[1], aAl0 + 1280 + kb);
      #pragma unroll
      for (int ntp=0; ntp<4; ntp++) {
        uint32_t bh4[4], bl4[4];
        ldm_x4(bh4, bBh0 + (uint32_t)ntp*1280 + kb);
        ldm_x4(bl4, bBl0 + (uint32_t)ntp*1280 + kb);
        int n0 = ntp*2, n1 = ntp*2+1;
        #pragma unroll
        for (int mt=0;mt<2;mt++) {
          mma16816(acc[mt][n0], ah[mt], bh4+0);
          mma16816(acc[mt][n0], ah[mt], bl4+0);
          mma16816(acc[mt][n0], al[mt], bh4+0);
          mma16816(acc[mt][n1], ah[mt], bh4+2);
          mma16816(acc[mt][n1], ah[mt], bl4+2);
          mma16816(acc[mt][n1], al[mt], bh4+2);
        }
      }
    }
    __syncthreads();
  }

  // fused scores epilogue: tanh.approx (1 MUFU) instead of software tanhf (2 MUFU + ~10 FMA)
  float* dst = (bn < 512) ? g_sg : g_sc;
  #pragma unroll
  for (int mt=0;mt<2;mt++) {
    #pragma unroll
    for (int rh=0; rh<2; rh++) {
      int row = bm + wm*32 + mt*16 + g + rh*8;
      int b = row / 600;
      int qs = (b == b_lo) ? 0 : 1;
      float s = 0.f;
      #pragma unroll
      for (int nt=0; nt<8; nt++) {
        int cl = wn*64 + nt*8 + t4*2;
        s += tanh_fast(s_q[qs][cl]   + acc[mt][nt][rh*2+0]) * s_av[cl];
        s += tanh_fast(s_q[qs][cl+1] + acc[mt][nt][rh*2+1]) * s_av[cl+1];
      }
      s += __shfl_xor_sync(0xffffffffu, s, 1);
      s += __shfl_xor_sync(0xffffffffu, s, 2);
      if (t4 == 0) atomicAdd(&dst[row], s);
    }
  }
}

// ---------------- small-M GEMM, float4 cols, K-split 32 + atomic accumulate ----------------
struct GArgs {
  const float* A0; const float* A1;
  const float* W0; const float* W1;
  const int* xidx; const float* emb;
  float* C;
  int K; int N;
};

enum { V_Z1=0, V_Z2=1, V_Q=2, V_HA=3 };

template<int VAR>
__device__ __forceinline__ float loadA(const GArgs& g, int b, int k) {
  if (VAR==V_Z1) {
    if (k < 300) return g.emb[(size_t)g.xidx[b]*300 + k];
    if (k < 812) return g.A0[b*512 + (k-300)];
    return g.A1[b*512 + (k-812)];
  }
  if (VAR==V_Z2 || VAR==V_HA) {
    if (k < 512) return g.A0[b*512+k];
    return g.A1[b*512 + (k-512)];
  }
  return g.A0[b*512+k]; // V_Q
}

template<int VAR>
__device__ __forceinline__ float4 loadW4(const GArgs& g, int k, int c) {
  if (VAR==V_Z1) return (k<812) ? *(const float4*)&g.W0[(size_t)k*2048+c]
                                : *(const float4*)&g.W1[(size_t)(k-812)*2048+c];
  if (VAR==V_Z2) return (k<512) ? *(const float4*)&g.W0[(size_t)k*2048+c]
                                : *(const float4*)&g.W1[(size_t)(k-512)*2048+c];
  if (VAR==V_Q)  return (c<512) ? *(const float4*)&g.W0[(size_t)k*512+c]
                                : *(const float4*)&g.W1[(size_t)k*512+(c-512)];
  return *(const float4*)&g.W0[(size_t)k*512+c]; // V_HA
}

#define ACC4(bi, av) \
  acc[bi].x = fmaf(av, w.x, acc[bi].x); acc[bi].y = fmaf(av, w.y, acc[bi].y); \
  acc[bi].z = fmaf(av, w.z, acc[bi].z); acc[bi].w = fmaf(av, w.w, acc[bi].w);

// grid: (N/512, ceil(K/32)); block: 128. Four columns per thread, 32-deep K slice.
template<int VAR>
__global__ void gemm16_atomic(GArgs g) {
  __shared__ __align__(16) float As[32][16];
  int tid = threadIdx.x;                 // 128
  int col = blockIdx.x*512 + tid*4;
  int k0  = blockIdx.y*32;

  #pragma unroll
  for (int i=0;i<4;i++) {
    int e = tid + i*128;                 // 0..511
    int kl = e >> 4, b = e & 15;
    int k = k0 + kl;
    As[kl][b] = (k < g.K) ? loadA<VAR>(g, b, k) : 0.f;
  }
  __syncthreads();

  float4 acc[16];
  #pragma unroll
  for (int b=0;b<16;b++) acc[b] = make_float4(0.f,0.f,0.f,0.f);

  int kmax = g.K - k0; if (kmax > 32) kmax = 32;
  #pragma unroll 4
  for (int kl=0; kl<kmax; kl++) {
    float4 w = loadW4<VAR>(g, k0+kl, col);
    const float4* ap = (const float4*)&As[kl][0];
    float4 v0 = ap[0], v1 = ap[1], v2 = ap[2], v3 = ap[3];
    ACC4(0, v0.x)  ACC4(1, v0.y)  ACC4(2, v0.z)  ACC4(3, v0.w)
    ACC4(4, v1.x)  ACC4(5, v1.y)  ACC4(6, v1.z)  ACC4(7, v1.w)
    ACC4(8, v2.x)  ACC4(9, v2.y)  ACC4(10,v2.z)  ACC4(11,v2.w)
    ACC4(12,v3.x)  ACC4(13,v3.y)  ACC4(14,v3.z)  ACC4(15,v3.w)
  }
  #pragma unroll
  for (int b=0;b<16;b++) {
    float* cp = &g.C[(size_t)b*g.N + col];
    atomicAdd(cp+0, acc[b].x); atomicAdd(cp+1, acc[b].y);
    atomicAdd(cp+2, acc[b].z); atomicAdd(cp+3, acc[b].w);
  }
}

// ---------------- logits: g_logits += ha @ Wg, float4 cols, K-split 8x64 ----------------
__global__ void gemm16_logits_split(const float* __restrict__ A, const float* __restrict__ W) {
  __shared__ __align__(16) float As[64][16];
  int tid = threadIdx.x;                 // 128
  int col = blockIdx.x*512 + tid*4;
  int k0  = blockIdx.y*64;
  #pragma unroll
  for (int i=0;i<8;i++) {
    int e = tid + i*128;
    int kl = e >> 4, b = e & 15;
    As[kl][b] = A[b*512 + k0 + kl];
  }
  __syncthreads();
  if (col >= VV) return;
  float4 acc[16];
  #pragma unroll
  for (int b=0;b<16;b++) acc[b] = make_float4(0.f,0.f,0.f,0.f);
  #pragma unroll 4
  for (int kl=0; kl<64; kl++) {
    float4 w = *(const float4*)&W[(size_t)(k0+kl)*VV + col];
    const float4* ap = (const float4*)&As[kl][0];
    float4 v0 = ap[0], v1 = ap[1], v2 = ap[2], v3 = ap[3];
    ACC4(0, v0.x)  ACC4(1, v0.y)  ACC4(2, v0.z)  ACC4(3, v0.w)
    ACC4(4, v1.x)  ACC4(5, v1.y)  ACC4(6, v1.z)  ACC4(7, v1.w)
    ACC4(8, v2.x)  ACC4(9, v2.y)  ACC4(10,v2.z)  ACC4(11,v2.w)
    ACC4(12,v3.x)  ACC4(13,v3.y)  ACC4(14,v3.z)  ACC4(15,v3.w)
  }
  #pragma unroll
  for (int b=0;b<16;b++) {
    float* cp = &g_logits[(size_t)b*VV + col];
    atomicAdd(cp+0, acc[b].x); atomicAdd(cp+1, acc[b].y);
    atomicAdd(cp+2, acc[b].z); atomicAdd(cp+3, acc[b].w);
  }
}

// ---------------- LSTM pointwise ----------------
__global__ void lstm_pw_kernel(const float* __restrict__ z, const float* __restrict__ cin,
                               float* __restrict__ hout, float* __restrict__ cout) {
  int idx = blockIdx.x*blockDim.x + threadIdx.x;
  if (idx >= BB*HH) return;
  int b = idx >> 9, j = idx & 511;
  const float* zb = z + b*2048;
  float iv = sigf(zb[j]);
  float fv = sigf(zb[512+j]);
  float gv = tanhf(zb[1024+j]);
  float ov = sigf(zb[1536+j]);
  float c = fv*cin[idx] + iv*gv;
  hout[idx] = ov*tanhf(c);
  cout[idx] = c;
}

// ---------------- softmax over T (both heads) ----------------
__global__ void softmax_kernel() {
  int b = blockIdx.x, tid = threadIdx.x;   // 256
  __shared__ float ag[TT], ac[TT];
  __shared__ float rbuf[256];
  for (int t=tid;t<TT;t+=256){ ag[t]=g_sg[b*TT+t]; ac[t]=g_sc[b*TT+t]; }
  __syncthreads();
  for (int pass=0; pass<2; pass++) {
    float* arr = pass ? ac : ag;
    float mx = -1e30f;
    for (int t=tid;t<TT;t+=256) mx = fmaxf(mx, arr[t]);
    rbuf[tid]=mx; __syncthreads();
    for (int s=128;s>0;s>>=1){ if (tid<s) rbuf[tid]=fmaxf(rbuf[tid],rbuf[tid+s]); __syncthreads(); }
    mx = rbuf[0]; __syncthreads();
    float ls=0.f;
    for (int t=tid;t<TT;t+=256){ float e=expf(arr[t]-mx); arr[t]=e; ls+=e; }
    rbuf[tid]=ls; __syncthreads();
    for (int s=128;s>0;s>>=1){ if (tid<s) rbuf[tid]+=rbuf[tid+s]; __syncthreads(); }
    float inv = 1.0f/rbuf[0]; __syncthreads();
    for (int t=tid;t<TT;t+=256) arr[t]*=inv;
    __syncthreads();
  }
  for (int t=tid;t<TT;t+=256){ g_aligng[b*TT+t]=ag[t]; g_alignc[b*TT+t]=ac[t]; }
}

// ---------------- context = align_g @ enc_outs, T-sliced + atomic ----------------
__global__ void ctx_kernel(const float* __restrict__ enc) {
  int s = blockIdx.x;            // 0..9
  int b = blockIdx.y;
  int tid = threadIdx.x;         // 512
  __shared__ float ag[60];
  if (tid < 60) ag[tid] = g_aligng[b*TT + s*60 + tid];
  __syncthreads();
  const float* eb = enc + (size_t)b*TT*HH + (size_t)(s*60)*HH + tid;
  float a0=0.f,a1=0.f,a2=0.f,a3=0.f,a4=0.f,a5=0.f;
  #pragma unroll 2
  for (int t=0;t<60;t+=6){
    a0 += ag[t]  *eb[(size_t)(t  )*HH];
    a1 += ag[t+1]*eb[(size_t)(t+1)*HH];
    a2 += ag[t+2]*eb[(size_t)(t+2)*HH];
    a3 += ag[t+3]*eb[(size_t)(t+3)*HH];
    a4 += ag[t+4]*eb[(size_t)(t+4)*HH];
    a5 += ag[t+5]*eb[(size_t)(t+5)*HH];
  }
  atomicAdd(&g_ctx[b*HH+tid], (a0+a1)+(a2+a3)+(a4+a5));
}

// ---------------- hidden_att finalize: tanh + switch ----------------
__global__ void ha_finalize_kernel(float* __restrict__ out_hidden,
                                   const float* __restrict__ Wf, const float* __restrict__ bf) {
  int b = blockIdx.x, tid = threadIdx.x;   // 512
  __shared__ float rb[512];
  float t = tanhf(g_ha[b*HH+tid]);
  out_hidden[b*HH+tid] = t;
  rb[tid] = t*Wf[tid];
  __syncthreads();
  for (int s=256;s>0;s>>=1){ if (tid<s) rb[tid]+=rb[tid+s]; __syncthreads(); }
  if (tid==0) g_switch[b] = sigf(rb[0]+bf[0]);
}

// ---------------- vocab softmax reductions, two-stage ----------------
__global__ void vred1_kernel() {
  int s = blockIdx.x, b = blockIdx.y;      // 10 x 16
  int tid = threadIdx.x;                   // 256
  __shared__ float rb[256];
  const float* lb = g_logits + (size_t)b*VV + s*2000;
  float mx = -1e30f;
  for (int i=tid;i<2000;i+=256) mx = fmaxf(mx, lb[i]);
  rb[tid]=mx; __syncthreads();
  for (int st=128;st>0;st>>=1){ if (tid<st) rb[tid]=fmaxf(rb[tid],rb[tid+st]); __syncthreads(); }
  mx = rb[0]; __syncthreads();
  float sm=0.f;
  for (int i=tid;i<2000;i+=256) sm += expf(lb[i]-mx);
  rb[tid]=sm; __syncthreads();
  for (int st=128;st>0;st>>=1){ if (tid<st) rb[tid]+=rb[tid+st]; __syncthreads(); }
  if (tid==0){ g_pm[b*10+s]=mx; g_ps[b*10+s]=rb[0]; }
}

__global__ void vred2_kernel() {
  int b = blockIdx.x, tid = threadIdx.x;   // 32
  float m = (tid<10) ? g_pm[b*10+tid] : -1e30f;
  #pragma unroll
  for (int o=16;o>0;o>>=1) m = fmaxf(m, __shfl_xor_sync(0xffffffffu, m, o));
  float s = (tid<10) ? g_ps[b*10+tid]*expf(g_pm[b*10+tid]-m) : 0.f;
  #pragma unroll
  for (int o=16;o>0;o>>=1) s += __shfl_xor_sync(0xffffffffu, s, o);
  if (tid==0){ g_vred[b*2]=m; g_vred[b*2+1]=s; }
}

// ---------------- final: copy_prob fp32 stream + mix ----------------
__global__ void final_kernel(const float* __restrict__ enc_ins, float* __restrict__ result) {
  int b = blockIdx.y, tid = threadIdx.x;   // 512
  int v = blockIdx.x*512 + tid;
  __shared__ float ac[TT];
  for (int t=tid;t<TT;t+=512) ac[t]=g_alignc[b*TT+t];
  __syncthreads();
  if (v >= VV) return;
  const float* eb = enc_ins + (size_t)b*TT*VV + v;
  float a0=0.f,a1=0.f,a2=0.f,a3=0.f,a4=0.f,a5=0.f,a6=0.f,a7=0.f;
  for (int t=0;t<TT;t+=8){
    a0 += ac[t]  * eb[(size_t)(t  )*VV];
    a1 += ac[t+1]* eb[(size_t)(t+1)*VV];
    a2 += ac[t+2]* eb[(size_t)(t+2)*VV];
    a3 += ac[t+3]* eb[(size_t)(t+3)*VV];
    a4 += ac[t+4]* eb[(size_t)(t+4)*VV];
    a5 += ac[t+5]* eb[(size_t)(t+5)*VV];
    a6 += ac[t+6]* eb[(size_t)(t+6)*VV];
    a7 += ac[t+7]* eb[(size_t)(t+7)*VV];
  }
  float copy = ((a0+a1)+(a2+a3))+((a4+a5)+(a6+a7));
  float sw = g_switch[b];
  float mx = g_vred[b*2], sm = g_vred[b*2+1];
  float gen = expf(g_logits[(size_t)b*VV+v]-mx)/sm;
  result[(size_t)b*VV+v] = gen*(1.0f-sw) + copy*sw;
}

// ---------------- launch ----------------
extern "C" void kernel_launch(void* const* d_in, const int* in_sizes, int n_in,
                              void* d_out, int out_size) {
  const int*   x        = (const int*)  d_in[0];
  const float* lha      = (const float*)d_in[1];
  const float* h1       = (const float*)d_in[2];
  const float* c1       = (const float*)d_in[3];
  const float* h2       = (const float*)d_in[4];
  const float* c2       = (const float*)d_in[5];
  const float* enc_outs = (const float*)d_in[6];
  const float* enc_ins  = (const float*)d_in[7];
  const float* emb      = (const float*)d_in[8];
  const float* k1       = (const float*)d_in[9];
  const float* r1       = (const float*)d_in[10];
  const float* b1       = (const float*)d_in[11];
  const float* k2       = (const float*)d_in[12];
  const float* r2       = (const float*)d_in[13];
  const float* b2       = (const float*)d_in[14];
  const float* Wh       = (const float*)d_in[15];
  const float* bh       = (const float*)d_in[16];
  const float* Wg       = (const float*)d_in[17];
  const float* bg       = (const float*)d_in[18];
  const float* Wf       = (const float*)d_in[19];
  const float* bf       = (const float*)d_in[20];
  const float* aw1g     = (const float*)d_in[21];
  const float* aw2g     = (const float*)d_in[22];
  const float* avg      = (const float*)d_in[23];
  const float* aw1c     = (const float*)d_in[24];
  const float* aw2c     = (const float*)d_in[25];
  const float* avc      = (const float*)d_in[26];

  float* out = (float*)d_out;
  float* out_result = out;                       // 16*20000
  float* out_hidden = out + BB*VV;
  float* out_h1n    = out_hidden + BB*HH;
  float* out_c1n    = out_h1n + BB*HH;
  float* out_h2n    = out_c1n + BB*HH;
  float* out_c2n    = out_h2n + BB*HH;

  float *p_z1, *p_z2, *p_q, *p_ctx, *p_ha;
  cudaGetSymbolAddress((void**)&p_z1, g_z1);
  cudaGetSymbolAddress((void**)&p_z2, g_z2);
  cudaGetSymbolAddress((void**)&p_q, g_q);
  cudaGetSymbolAddress((void**)&p_ctx, g_ctx);
  cudaGetSymbolAddress((void**)&p_ha, g_ha);

  // side stream for the bf16 prep of the attention GEMM (overlaps LSTM chain)
  cudaStream_t s2;
  cudaStreamCreateWithFlags(&s2, cudaStreamNonBlocking);
  cudaEvent_t evFork, evJ1;
  cudaEventCreateWithFlags(&evFork, cudaEventDisableTiming);
  cudaEventCreateWithFlags(&evJ1, cudaEventDisableTiming);

  cudaEventRecord(evFork, 0);
  cudaStreamWaitEvent(s2, evFork, 0);

  convA_kernel<<<(BT*512/4 + 255)/256, 256, 0, s2>>>(enc_outs);
  convW_kernel<<<dim3(16,32), 256, 0, s2>>>(aw2g, aw2c);
  cudaEventRecord(evJ1, s2);

  // main stream: init + LSTM chain
  init_kernel<<<(INIT_TOTAL+255)/256, 256>>>(b1, b2, bh, bg);

  GArgs az1; az1.A0=lha; az1.A1=h1; az1.W0=k1; az1.W1=r1;
  az1.xidx=x; az1.emb=emb; az1.C=p_z1; az1.K=1324; az1.N=2048;
  gemm16_atomic<V_Z1><<<dim3(4,42),128>>>(az1);
  lstm_pw_kernel<<<32,256>>>(p_z1, c1, out_h1n, out_c1n);

  GArgs az2; az2.A0=out_h1n; az2.A1=h2; az2.W0=k2; az2.W1=r2;
  az2.xidx=nullptr; az2.emb=nullptr; az2.C=p_z2; az2.K=1024; az2.N=2048;
  gemm16_atomic<V_Z2><<<dim3(4,32),128>>>(az2);
  lstm_pw_kernel<<<32,256>>>(p_z2, c2, out_h2n, out_c2n);

  GArgs aq; aq.A0=out_h2n; aq.A1=nullptr; aq.W0=aw1g; aq.W1=aw1c;
  aq.xidx=nullptr; aq.emb=nullptr; aq.C=p_q; aq.K=512; aq.N=1024;
  gemm16_atomic<V_Q><<<dim3(2,16),128>>>(aq);

  // join: need bf16 enc/W for mma
  cudaStreamWaitEvent(0, evJ1, 0);
  mma_attn_scores_kernel<<<dim3(75,8), 256>>>(avg, avc);

  softmax_kernel<<<BB,256>>>();
  ctx_kernel<<<dim3(10,BB),512>>>(enc_outs);

  GArgs aha; aha.A0=p_ctx; aha.A1=out_h2n; aha.W0=Wh; aha.W1=nullptr;
  aha.xidx=nullptr; aha.emb=nullptr; aha.C=p_ha; aha.K=1024; aha.N=512;
  gemm16_atomic<V_HA><<<dim3(1,32),128>>>(aha);
  ha_finalize_kernel<<<BB,512>>>(out_hidden, Wf, bf);

  gemm16_logits_split<<<dim3(40,8),128>>>(out_hidden, Wg);
  vred1_kernel<<<dim3(10,BB),256>>>();
  vred2_kernel<<<BB,32>>>();

  final_kernel<<<dim3((VV+511)/512, BB), 512>>>(enc_ins, out_result);
}

// round 11
// speedup vs baseline: 1.4563x; 1.0397x over previous
#include <cuda_runtime.h>
#include <cuda_bf16.h>
#include <math.h>
#include <stdint.h>

#define BB 16
#define TT 600
#define VV 20000
#define EE 300
#define HH 512
#define BT (BB*TT)   // 9600

// ---------------- scratch ----------------
__device__ uint32_t g_A2h[(size_t)BT*256];   // enc hi, bf16 [9600][512] packed as u32
__device__ uint32_t g_A2l[(size_t)BT*256];   // enc lo
__device__ uint32_t g_Wth[1024*256];         // W^T hi, bf16 [1024 n][512 k]
__device__ uint32_t g_Wtl[1024*256];         // W^T lo
__device__ float g_z1[BB*2048];
__device__ float g_z2[BB*2048];
__device__ float g_q[BB*1024];
__device__ float g_ha[BB*HH];
__device__ float g_sg[BB*TT];
__device__ float g_sc[BB*TT];
__device__ float g_aligng[BB*TT];
__device__ float g_alignc[BB*TT];
__device__ float g_ctx[BB*HH];
__device__ float g_logits[(size_t)BB*VV];
__device__ float g_pm[BB*10];
__device__ float g_ps[BB*10];
__device__ float g_vred[BB*2];
__device__ float g_switch[BB];

__device__ __forceinline__ float sigf(float x){ return 1.0f/(1.0f+expf(-x)); }

__device__ __forceinline__ float tanh_fast(float x){
  float y;
  asm("tanh.approx.f32 %0, %1;" : "=f"(y) : "f"(x));
  return y;
}

// ---------------- init: biases / zeros into accumulators ----------------
#define INIT_TOTAL (117504 + 320000)
__global__ void init_kernel(const float* __restrict__ b1, const float* __restrict__ b2,
                            const float* __restrict__ bh, const float* __restrict__ bg) {
  int idx = blockIdx.x*blockDim.x + threadIdx.x;
  if (idx < 32768)            g_z1[idx] = b1[idx & 2047];
  else if (idx < 65536)       g_z2[idx-32768] = b2[idx & 2047];
  else if (idx < 81920)       g_q[idx-65536] = 0.f;
  else if (idx < 90112)       g_ha[idx-81920] = bh[idx & 511];
  else if (idx < 98304)       g_ctx[idx-90112] = 0.f;
  else if (idx < 107904)      g_sg[idx-98304] = 0.f;
  else if (idx < 117504)      g_sc[idx-107904] = 0.f;
  else if (idx < INIT_TOTAL) {
    int e = idx - 117504;
    g_logits[e] = bg[e % VV];
  }
}

// ---------------- convert enc_outs -> bf16 hi/lo ----------------
__global__ void convA_kernel(const float* __restrict__ A) {
  int i4 = blockIdx.x*blockDim.x + threadIdx.x;
  if (i4 >= BT*512/4) return;
  float4 v = *(const float4*)&A[i4*4];
  __nv_bfloat16 h0 = __float2bfloat16(v.x);
  __nv_bfloat16 h1 = __float2bfloat16(v.y);
  __nv_bfloat16 h2 = __float2bfloat16(v.z);
  __nv_bfloat16 h3 = __float2bfloat16(v.w);
  __nv_bfloat16 l0 = __float2bfloat16(v.x - __bfloat162float(h0));
  __nv_bfloat16 l1 = __float2bfloat16(v.y - __bfloat162float(h1));
  __nv_bfloat16 l2 = __float2bfloat16(v.z - __bfloat162float(h2));
  __nv_bfloat16 l3 = __float2bfloat16(v.w - __bfloat162float(h3));
  __nv_bfloat162* ph = (__nv_bfloat162*)g_A2h;
  __nv_bfloat162* pl = (__nv_bfloat162*)g_A2l;
  ph[i4*2]   = __nv_bfloat162(h0,h1);
  ph[i4*2+1] = __nv_bfloat162(h2,h3);
  pl[i4*2]   = __nv_bfloat162(l0,l1);
  pl[i4*2+1] = __nv_bfloat162(l2,l3);
}

// ---------------- transpose + convert W -> Wt bf16 hi/lo ----------------
__global__ void convW_kernel(const float* __restrict__ Wg, const float* __restrict__ Wc) {
  __shared__ float tile[32][33];
  int k0 = blockIdx.x*32;
  int n0 = blockIdx.y*32;
  const float* W = (n0 < 512) ? Wg : Wc;
  int nn0 = n0 & 511;
  int tx = threadIdx.x & 31, ty = threadIdx.x >> 5;
  #pragma unroll
  for (int i=0;i<4;i++) {
    int k = k0 + ty + i*8;
    tile[ty+i*8][tx] = W[(size_t)k*512 + nn0 + tx];
  }
  __syncthreads();
  __nv_bfloat16* WH = (__nv_bfloat16*)g_Wth;
  __nv_bfloat16* WL = (__nv_bfloat16*)g_Wtl;
  #pragma unroll
  for (int i=0;i<4;i++) {
    int n = n0 + ty + i*8;
    float x = tile[tx][ty+i*8];
    __nv_bfloat16 h = __float2bfloat16(x);
    WH[(size_t)n*512 + k0 + tx] = h;
    WL[(size_t)n*512 + k0 + tx] = __float2bfloat16(x - __bfloat162float(h));
  }
}

// ---------------- mma helpers ----------------
__device__ __forceinline__ void mma16816(float* c, const uint32_t* a, const uint32_t* b) {
  asm volatile(
    "mma.sync.aligned.m16n8k16.row.col.f32.bf16.bf16.f32 "
    "{%0,%1,%2,%3}, {%4,%5,%6,%7}, {%8,%9}, {%0,%1,%2,%3};"
    : "+f"(c[0]), "+f"(c[1]), "+f"(c[2]), "+f"(c[3])
    : "r"(a[0]), "r"(a[1]), "r"(a[2]), "r"(a[3]), "r"(b[0]), "r"(b[1]));
}

__device__ __forceinline__ void ldm_x4(uint32_t* r, uint32_t addr) {
  asm volatile("ldmatrix.sync.aligned.m8n8.x4.shared.b16 {%0,%1,%2,%3}, [%4];"
    : "=r"(r[0]), "=r"(r[1]), "=r"(r[2]), "=r"(r[3]) : "r"(addr));
}

// ---------------- fused: P = enc @ [aw2g|aw2c]; scores += tanh(q+P)*av ----------------
__global__ void __launch_bounds__(256, 2) mma_attn_scores_kernel(
    const float* __restrict__ avg, const float* __restrict__ avc) {
  __shared__ uint32_t sAh[128*20];
  __shared__ uint32_t sAl[128*20];
  __shared__ uint32_t sBh[128*20];
  __shared__ uint32_t sBl[128*20];
  __shared__ float s_av[128];
  __shared__ float s_q[2][128];

  int tid = threadIdx.x;
  int bm = blockIdx.x * 128;     // 75
  int bn = blockIdx.y * 128;     // 8
  int wid = tid >> 5, lane = tid & 31;
  int wm = wid >> 1, wn = wid & 1;
  int g = lane >> 2, t4 = lane & 3;

  int b_lo = bm / 600;
  int b_hi = (bm + 127) / 600;
  if (tid < 128) {
    const float* av = (bn < 512) ? avg : avc;
    s_av[tid] = av[(bn & 511) + tid];
    s_q[0][tid] = g_q[b_lo*1024 + bn + tid];
    s_q[1][tid] = g_q[b_hi*1024 + bn + tid];
  }

  uint32_t baseAh = (uint32_t)__cvta_generic_to_shared(sAh);
  uint32_t baseAl = (uint32_t)__cvta_generic_to_shared(sAl);
  uint32_t baseBh = (uint32_t)__cvta_generic_to_shared(sBh);
  uint32_t baseBl = (uint32_t)__cvta_generic_to_shared(sBl);
  uint32_t aoff = ((uint32_t)((wm*32 + (lane & 15))*20 + (lane >> 4)*4)) * 4;
  uint32_t aAh0 = baseAh + aoff, aAl0 = baseAl + aoff;
  uint32_t boff = ((uint32_t)((wn*64 + (lane & 7) + ((lane >> 4) << 3))*20 + ((lane >> 3) & 1)*4)) * 4;
  uint32_t bBh0 = baseBh + boff, bBl0 = baseBl + boff;

  float acc[2][8][4];
  #pragma unroll
  for (int mt=0;mt<2;mt++)
    #pragma unroll
    for (int nt=0;nt<8;nt++)
      #pragma unroll
      for (int r=0;r<4;r++) acc[mt][nt][r]=0.f;

  for (int kc=0; kc<512; kc+=32) {
    #pragma unroll
    for (int i=0;i<8;i++) {
      int e = tid + i*256;
      int row = e >> 4, kw = e & 15;
      size_t ga = (size_t)(bm+row)*256 + (kc>>1) + kw;
      size_t gb = (size_t)(bn+row)*256 + (kc>>1) + kw;
      int ss = row*20 + kw;
      sAh[ss] = g_A2h[ga];
      sAl[ss] = g_A2l[ga];
      sBh[ss] = g_Wth[gb];
      sBl[ss] = g_Wtl[gb];
    }
    __syncthreads();

    #pragma unroll
    for (int ks=0; ks<2; ks++) {
      uint32_t kb = ks*32;
      uint32_t ah[2][4], al[2][4];
      ldm_x4(ah[0], aAh0 + kb);
      ldm_x4(ah[1], aAh0 + 1280 + kb);
      ldm_x4(al[0], aAl0 + kb);
      ldm_x4(al[1], aAl0 + 1280 + kb);
      #pragma unroll
      for (int ntp=0; ntp<4; ntp++) {
        uint32_t bh4[4], bl4[4];
        ldm_x4(bh4, bBh0 + (uint32_t)ntp*1280 + kb);
        ldm_x4(bl4, bBl0 + (uint32_t)ntp*1280 + kb);
        int n0 = ntp*2, n1 = ntp*2+1;
        #pragma unroll
        for (int mt=0;mt<2;mt++) {
          mma16816(acc[mt][n0], ah[mt], bh4+0);
          mma16816(acc[mt][n0], ah[mt], bl4+0);
          mma16816(acc[mt][n0], al[mt], bh4+0);
          mma16816(acc[mt][n1], ah[mt], bh4+2);
          mma16816(acc[mt][n1], ah[mt], bl4+2);
          mma16816(acc[mt][n1], al[mt], bh4+2);
        }
      }
    }
    __syncthreads();
  }

  // fused scores epilogue with tanh.approx
  float* dst = (bn < 512) ? g_sg : g_sc;
  #pragma unroll
  for (int mt=0;mt<2;mt++) {
    #pragma unroll
    for (int rh=0; rh<2; rh++) {
      int row = bm + wm*32 + mt*16 + g + rh*8;
      int b = row / 600;
      int qs = (b == b_lo) ? 0 : 1;
      float s = 0.f;
      #pragma unroll
      for (int nt=0; nt<8; nt++) {
        int cl = wn*64 + nt*8 + t4*2;
        s += tanh_fast(s_q[qs][cl]   + acc[mt][nt][rh*2+0]) * s_av[cl];
        s += tanh_fast(s_q[qs][cl+1] + acc[mt][nt][rh*2+1]) * s_av[cl+1];
      }
      s += __shfl_xor_sync(0xffffffffu, s, 1);
      s += __shfl_xor_sync(0xffffffffu, s, 2);
      if (t4 == 0) atomicAdd(&dst[row], s);
    }
  }
}

// ---------------- small-M GEMM, batched float4 loads, K-split 32 + atomics ----------------
struct GArgs {
  const float* A0; const float* A1;
  const float* W0; const float* W1;
  const int* xidx; const float* emb;
  float* C;
  int K; int N;
};

enum { V_Z1=0, V_Z2=1, V_Q=2, V_HA=3 };

template<int VAR>
__device__ __forceinline__ float loadA(const GArgs& g, int b, int k) {
  if (VAR==V_Z1) {
    if (k < 300) return g.emb[(size_t)g.xidx[b]*300 + k];
    if (k < 812) return g.A0[b*512 + (k-300)];
    return g.A1[b*512 + (k-812)];
  }
  if (VAR==V_Z2 || VAR==V_HA) {
    if (k < 512) return g.A0[b*512+k];
    return g.A1[b*512 + (k-512)];
  }
  return g.A0[b*512+k]; // V_Q
}

// address-select form: SEL on pointer, single batchable LDG.128
template<int VAR>
__device__ __forceinline__ const float4* addrW4(const GArgs& g, int k, int c) {
  if (VAR==V_Z1) {
    const float* p = (k<812) ? (g.W0 + (size_t)k*2048) : (g.W1 + (size_t)(k-812)*2048);
    return (const float4*)(p + c);
  }
  if (VAR==V_Z2) {
    const float* p = (k<512) ? (g.W0 + (size_t)k*2048) : (g.W1 + (size_t)(k-512)*2048);
    return (const float4*)(p + c);
  }
  if (VAR==V_Q) {
    const float* p = (c<512) ? (g.W0 + (size_t)k*512 + c) : (g.W1 + (size_t)k*512 + (c-512));
    return (const float4*)p;
  }
  return (const float4*)(g.W0 + (size_t)k*512 + c); // V_HA
}

#define ACC4(bi, av) \
  acc[bi].x = fmaf(av, w.x, acc[bi].x); acc[bi].y = fmaf(av, w.y, acc[bi].y); \
  acc[bi].z = fmaf(av, w.z, acc[bi].z); acc[bi].w = fmaf(av, w.w, acc[bi].w);

// grid: (N/512, ceil(K/32)); block: 128. Four columns per thread, 32-deep K slice.
// Inner loop: 8 independent LDG.128 front-batched, then 8x64 FMA.
template<int VAR>
__global__ void gemm16_atomic(GArgs g) {
  __shared__ __align__(16) float As[32][16];
  int tid = threadIdx.x;                 // 128
  int col = blockIdx.x*512 + tid*4;
  int k0  = blockIdx.y*32;

  #pragma unroll
  for (int i=0;i<4;i++) {
    int e = tid + i*128;                 // 0..511
    int kl = e >> 4, b = e & 15;
    int k = k0 + kl;
    As[kl][b] = (k < g.K) ? loadA<VAR>(g, b, k) : 0.f;
  }
  __syncthreads();

  float4 acc[16];
  #pragma unroll
  for (int b=0;b<16;b++) acc[b] = make_float4(0.f,0.f,0.f,0.f);

  #pragma unroll
  for (int kb=0; kb<32; kb+=8) {
    // phase 1: issue 8 independent loads (MLP 8)
    float4 wb[8];
    #pragma unroll
    for (int j=0;j<8;j++) {
      int k = k0 + kb + j;
      wb[j] = (k < g.K) ? *addrW4<VAR>(g, k, col) : make_float4(0.f,0.f,0.f,0.f);
    }
    // phase 2: consume
    #pragma unroll
    for (int j=0;j<8;j++) {
      float4 w = wb[j];
      const float4* ap = (const float4*)&As[kb+j][0];
      float4 v0 = ap[0], v1 = ap[1], v2 = ap[2], v3 = ap[3];
      ACC4(0, v0.x)  ACC4(1, v0.y)  ACC4(2, v0.z)  ACC4(3, v0.w)
      ACC4(4, v1.x)  ACC4(5, v1.y)  ACC4(6, v1.z)  ACC4(7, v1.w)
      ACC4(8, v2.x)  ACC4(9, v2.y)  ACC4(10,v2.z)  ACC4(11,v2.w)
      ACC4(12,v3.x)  ACC4(13,v3.y)  ACC4(14,v3.z)  ACC4(15,v3.w)
    }
  }
  #pragma unroll
  for (int b=0;b<16;b++) {
    float* cp = &g.C[(size_t)b*g.N + col];
    atomicAdd(cp+0, acc[b].x); atomicAdd(cp+1, acc[b].y);
    atomicAdd(cp+2, acc[b].z); atomicAdd(cp+3, acc[b].w);
  }
}

// ---------------- logits: g_logits += ha @ Wg, batched loads, K-split 8x64 ----------------
__global__ void gemm16_logits_split(const float* __restrict__ A, const float* __restrict__ W) {
  __shared__ __align__(16) float As[64][16];
  int tid = threadIdx.x;                 // 128
  int col = blockIdx.x*512 + tid*4;
  int k0  = blockIdx.y*64;
  #pragma unroll
  for (int i=0;i<8;i++) {
    int e = tid + i*128;
    int kl = e >> 4, b = e & 15;
    As[kl][b] = A[b*512 + k0 + kl];
  }
  __syncthreads();
  if (col >= VV) return;
  float4 acc[16];
  #pragma unroll
  for (int b=0;b<16;b++) acc[b] = make_float4(0.f,0.f,0.f,0.f);

  #pragma unroll
  for (int kb=0; kb<64; kb+=8) {
    float4 wb[8];
    #pragma unroll
    for (int j=0;j<8;j++)
      wb[j] = *(const float4*)&W[(size_t)(k0+kb+j)*VV + col];
    #pragma unroll
    for (int j=0;j<8;j++) {
      float4 w = wb[j];
      const float4* ap = (const float4*)&As[kb+j][0];
      float4 v0 = ap[0], v1 = ap[1], v2 = ap[2], v3 = ap[3];
      ACC4(0, v0.x)  ACC4(1, v0.y)  ACC4(2, v0.z)  ACC4(3, v0.w)
      ACC4(4, v1.x)  ACC4(5, v1.y)  ACC4(6, v1.z)  ACC4(7, v1.w)
      ACC4(8, v2.x)  ACC4(9, v2.y)  ACC4(10,v2.z)  ACC4(11,v2.w)
      ACC4(12,v3.x)  ACC4(13,v3.y)  ACC4(14,v3.z)  ACC4(15,v3.w)
    }
  }
  #pragma unroll
  for (int b=0;b<16;b++) {
    float* cp = &g_logits[(size_t)b*VV + col];
    atomicAdd(cp+0, acc[b].x); atomicAdd(cp+1, acc[b].y);
    atomicAdd(cp+2, acc[b].z); atomicAdd(cp+3, acc[b].w);
  }
}

// ---------------- LSTM pointwise ----------------
__global__ void lstm_pw_kernel(const float* __restrict__ z, const float* __restrict__ cin,
                               float* __restrict__ hout, float* __restrict__ cout) {
  int idx = blockIdx.x*blockDim.x + threadIdx.x;
  if (idx >= BB*HH) return;
  int b = idx >> 9, j = idx & 511;
  const float* zb = z + b*2048;
  float iv = sigf(zb[j]);
  float fv = sigf(zb[512+j]);
  float gv = tanhf(zb[1024+j]);
  float ov = sigf(zb[1536+j]);
  float c = fv*cin[idx] + iv*gv;
  hout[idx] = ov*tanhf(c);
  cout[idx] = c;
}

// ---------------- softmax over T (both heads) ----------------
__global__ void softmax_kernel() {
  int b = blockIdx.x, tid = threadIdx.x;   // 256
  __shared__ float ag[TT], ac[TT];
  __shared__ float rbuf[256];
  for (int t=tid;t<TT;t+=256){ ag[t]=g_sg[b*TT+t]; ac[t]=g_sc[b*TT+t]; }
  __syncthreads();
  for (int pass=0; pass<2; pass++) {
    float* arr = pass ? ac : ag;
    float mx = -1e30f;
    for (int t=tid;t<TT;t+=256) mx = fmaxf(mx, arr[t]);
    rbuf[tid]=mx; __syncthreads();
    for (int s=128;s>0;s>>=1){ if (tid<s) rbuf[tid]=fmaxf(rbuf[tid],rbuf[tid+s]); __syncthreads(); }
    mx = rbuf[0]; __syncthreads();
    float ls=0.f;
    for (int t=tid;t<TT;t+=256){ float e=expf(arr[t]-mx); arr[t]=e; ls+=e; }
    rbuf[tid]=ls; __syncthreads();
    for (int s=128;s>0;s>>=1){ if (tid<s) rbuf[tid]+=rbuf[tid+s]; __syncthreads(); }
    float inv = 1.0f/rbuf[0]; __syncthreads();
    for (int t=tid;t<TT;t+=256) arr[t]*=inv;
    __syncthreads();
  }
  for (int t=tid;t<TT;t+=256){ g_aligng[b*TT+t]=ag[t]; g_alignc[b*TT+t]=ac[t]; }
}

// ---------------- context = align_g @ enc_outs, T-sliced + atomic ----------------
__global__ void ctx_kernel(const float* __restrict__ enc) {
  int s = blockIdx.x;            // 0..9
  int b = blockIdx.y;
  int tid = threadIdx.x;         // 512
  __shared__ float ag[60];
  if (tid < 60) ag[tid] = g_aligng[b*TT + s*60 + tid];
  __syncthreads();
  const float* eb = enc + (size_t)b*TT*HH + (size_t)(s*60)*HH + tid;
  float a0=0.f,a1=0.f,a2=0.f,a3=0.f,a4=0.f,a5=0.f;
  #pragma unroll 2
  for (int t=0;t<60;t+=6){
    a0 += ag[t]  *eb[(size_t)(t  )*HH];
    a1 += ag[t+1]*eb[(size_t)(t+1)*HH];
    a2 += ag[t+2]*eb[(size_t)(t+2)*HH];
    a3 += ag[t+3]*eb[(size_t)(t+3)*HH];
    a4 += ag[t+4]*eb[(size_t)(t+4)*HH];
    a5 += ag[t+5]*eb[(size_t)(t+5)*HH];
  }
  atomicAdd(&g_ctx[b*HH+tid], (a0+a1)+(a2+a3)+(a4+a5));
}

// ---------------- hidden_att finalize: tanh + switch ----------------
__global__ void ha_finalize_kernel(float* __restrict__ out_hidden,
                                   const float* __restrict__ Wf, const float* __restrict__ bf) {
  int b = blockIdx.x, tid = threadIdx.x;   // 512
  __shared__ float rb[512];
  float t = tanhf(g_ha[b*HH+tid]);
  out_hidden[b*HH+tid] = t;
  rb[tid] = t*Wf[tid];
  __syncthreads();
  for (int s=256;s>0;s>>=1){ if (tid<s) rb[tid]+=rb[tid+s]; __syncthreads(); }
  if (tid==0) g_switch[b] = sigf(rb[0]+bf[0]);
}

// ---------------- vocab softmax reductions, two-stage ----------------
__global__ void vred1_kernel() {
  int s = blockIdx.x, b = blockIdx.y;      // 10 x 16
  int tid = threadIdx.x;                   // 256
  __shared__ float rb[256];
  const float* lb = g_logits + (size_t)b*VV + s*2000;
  float mx = -1e30f;
  for (int i=tid;i<2000;i+=256) mx = fmaxf(mx, lb[i]);
  rb[tid]=mx; __syncthreads();
  for (int st=128;st>0;st>>=1){ if (tid<st) rb[tid]=fmaxf(rb[tid],rb[tid+st]); __syncthreads(); }
  mx = rb[0]; __syncthreads();
  float sm=0.f;
  for (int i=tid;i<2000;i+=256) sm += expf(lb[i]-mx);
  rb[tid]=sm; __syncthreads();
  for (int st=128;st>0;st>>=1){ if (tid<st) rb[tid]+=rb[tid+st]; __syncthreads(); }
  if (tid==0){ g_pm[b*10+s]=mx; g_ps[b*10+s]=rb[0]; }
}

__global__ void vred2_kernel() {
  int b = blockIdx.x, tid = threadIdx.x;   // 32
  float m = (tid<10) ? g_pm[b*10+tid] : -1e30f;
  #pragma unroll
  for (int o=16;o>0;o>>=1) m = fmaxf(m, __shfl_xor_sync(0xffffffffu, m, o));
  float s = (tid<10) ? g_ps[b*10+tid]*expf(g_pm[b*10+tid]-m) : 0.f;
  #pragma unroll
  for (int o=16;o>0;o>>=1) s += __shfl_xor_sync(0xffffffffu, s, o);
  if (tid==0){ g_vred[b*2]=m; g_vred[b*2+1]=s; }
}

// ---------------- final: copy_prob fp32 stream + mix ----------------
__global__ void final_kernel(const float* __restrict__ enc_ins, float* __restrict__ result) {
  int b = blockIdx.y, tid = threadIdx.x;   // 512
  int v = blockIdx.x*512 + tid;
  __shared__ float ac[TT];
  for (int t=tid;t<TT;t+=512) ac[t]=g_alignc[b*TT+t];
  __syncthreads();
  if (v >= VV) return;
  const float* eb = enc_ins + (size_t)b*TT*VV + v;
  float a0=0.f,a1=0.f,a2=0.f,a3=0.f,a4=0.f,a5=0.f,a6=0.f,a7=0.f;
  for (int t=0;t<TT;t+=8){
    a0 += ac[t]  * eb[(size_t)(t  )*VV];
    a1 += ac[t+1]* eb[(size_t)(t+1)*VV];
    a2 += ac[t+2]* eb[(size_t)(t+2)*VV];
    a3 += ac[t+3]* eb[(size_t)(t+3)*VV];
    a4 += ac[t+4]* eb[(size_t)(t+4)*VV];
    a5 += ac[t+5]* eb[(size_t)(t+5)*VV];
    a6 += ac[t+6]* eb[(size_t)(t+6)*VV];
    a7 += ac[t+7]* eb[(size_t)(t+7)*VV];
  }
  float copy = ((a0+a1)+(a2+a3))+((a4+a5)+(a6+a7));
  float sw = g_switch[b];
  float mx = g_vred[b*2], sm = g_vred[b*2+1];
  float gen = expf(g_logits[(size_t)b*VV+v]-mx)/sm;
  result[(size_t)b*VV+v] = gen*(1.0f-sw) + copy*sw;
}

// ---------------- launch ----------------
extern "C" void kernel_launch(void* const* d_in, const int* in_sizes, int n_in,
                              void* d_out, int out_size) {
  const int*   x        = (const int*)  d_in[0];
  const float* lha      = (const float*)d_in[1];
  const float* h1       = (const float*)d_in[2];
  const float* c1       = (const float*)d_in[3];
  const float* h2       = (const float*)d_in[4];
  const float* c2       = (const float*)d_in[5];
  const float* enc_outs = (const float*)d_in[6];
  const float* enc_ins  = (const float*)d_in[7];
  const float* emb      = (const float*)d_in[8];
  const float* k1       = (const float*)d_in[9];
  const float* r1       = (const float*)d_in[10];
  const float* b1       = (const float*)d_in[11];
  const float* k2       = (const float*)d_in[12];
  const float* r2       = (const float*)d_in[13];
  const float* b2       = (const float*)d_in[14];
  const float* Wh       = (const float*)d_in[15];
  const float* bh       = (const float*)d_in[16];
  const float* Wg       = (const float*)d_in[17];
  const float* bg       = (const float*)d_in[18];
  const float* Wf       = (const float*)d_in[19];
  const float* bf       = (const float*)d_in[20];
  const float* aw1g     = (const float*)d_in[21];
  const float* aw2g     = (const float*)d_in[22];
  const float* avg      = (const float*)d_in[23];
  const float* aw1c     = (const float*)d_in[24];
  const float* aw2c     = (const float*)d_in[25];
  const float* avc      = (const float*)d_in[26];

  float* out = (float*)d_out;
  float* out_result = out;                       // 16*20000
  float* out_hidden = out + BB*VV;
  float* out_h1n    = out_hidden + BB*HH;
  float* out_c1n    = out_h1n + BB*HH;
  float* out_h2n    = out_c1n + BB*HH;
  float* out_c2n    = out_h2n + BB*HH;

  float *p_z1, *p_z2, *p_q, *p_ctx, *p_ha;
  cudaGetSymbolAddress((void**)&p_z1, g_z1);
  cudaGetSymbolAddress((void**)&p_z2, g_z2);
  cudaGetSymbolAddress((void**)&p_q, g_q);
  cudaGetSymbolAddress((void**)&p_ctx, g_ctx);
  cudaGetSymbolAddress((void**)&p_ha, g_ha);

  // side stream for the bf16 prep of the attention GEMM (overlaps LSTM chain)
  cudaStream_t s2;
  cudaStreamCreateWithFlags(&s2, cudaStreamNonBlocking);
  cudaEvent_t evFork, evJ1;
  cudaEventCreateWithFlags(&evFork, cudaEventDisableTiming);
  cudaEventCreateWithFlags(&evJ1, cudaEventDisableTiming);

  cudaEventRecord(evFork, 0);
  cudaStreamWaitEvent(s2, evFork, 0);

  convA_kernel<<<(BT*512/4 + 255)/256, 256, 0, s2>>>(enc_outs);
  convW_kernel<<<dim3(16,32), 256, 0, s2>>>(aw2g, aw2c);
  cudaEventRecord(evJ1, s2);

  // main stream: init + LSTM chain
  init_kernel<<<(INIT_TOTAL+255)/256, 256>>>(b1, b2, bh, bg);

  GArgs az1; az1.A0=lha; az1.A1=h1; az1.W0=k1; az1.W1=r1;
  az1.xidx=x; az1.emb=emb; az1.C=p_z1; az1.K=1324; az1.N=2048;
  gemm16_atomic<V_Z1><<<dim3(4,42),128>>>(az1);
  lstm_pw_kernel<<<32,256>>>(p_z1, c1, out_h1n, out_c1n);

  GArgs az2; az2.A0=out_h1n; az2.A1=h2; az2.W0=k2; az2.W1=r2;
  az2.xidx=nullptr; az2.emb=nullptr; az2.C=p_z2; az2.K=1024; az2.N=2048;
  gemm16_atomic<V_Z2><<<dim3(4,32),128>>>(az2);
  lstm_pw_kernel<<<32,256>>>(p_z2, c2, out_h2n, out_c2n);

  GArgs aq; aq.A0=out_h2n; aq.A1=nullptr; aq.W0=aw1g; aq.W1=aw1c;
  aq.xidx=nullptr; aq.emb=nullptr; aq.C=p_q; aq.K=512; aq.N=1024;
  gemm16_atomic<V_Q><<<dim3(2,16),128>>>(aq);

  // join: need bf16 enc/W for mma
  cudaStreamWaitEvent(0, evJ1, 0);
  mma_attn_scores_kernel<<<dim3(75,8), 256>>>(avg, avc);

  softmax_kernel<<<BB,256>>>();
  ctx_kernel<<<dim3(10,BB),512>>>(enc_outs);

  GArgs aha; aha.A0=p_ctx; aha.A1=out_h2n; aha.W0=Wh; aha.W1=nullptr;
  aha.xidx=nullptr; aha.emb=nullptr; aha.C=p_ha; aha.K=1024; aha.N=512;
  gemm16_atomic<V_HA><<<dim3(1,32),128>>>(aha);
  ha_finalize_kernel<<<BB,512>>>(out_hidden, Wf, bf);

  gemm16_logits_split<<<dim3(40,8),128>>>(out_hidden, Wg);
  vred1_kernel<<<dim3(10,BB),256>>>();
  vred2_kernel<<<BB,32>>>();

  final_kernel<<<dim3((VV+511)/512, BB), 512>>>(enc_ins, out_result);
}

// round 12
// speedup vs baseline: 1.5314x; 1.0515x over previous
#include <cuda_runtime.h>
#include <cuda_bf16.h>
#include <math.h>
#include <stdint.h>

#define BB 16
#define TT 600
#define VV 20000
#define EE 300
#define HH 512
#define BT (BB*TT)   // 9600

// ---------------- scratch ----------------
__device__ uint32_t g_A2h[(size_t)BT*256];   // enc hi, bf16 [9600][512] packed as u32
__device__ uint32_t g_A2l[(size_t)BT*256];   // enc lo
__device__ uint32_t g_Wth[1024*256];         // W^T hi, bf16 [1024 n][512 k]
__device__ uint32_t g_Wtl[1024*256];         // W^T lo
__device__ float g_z1[BB*2048];
__device__ float g_z2[BB*2048];
__device__ float g_q[BB*1024];
__device__ float g_ha[BB*HH];
__device__ float g_sg[BB*TT];
__device__ float g_sc[BB*TT];
__device__ float g_aligng[BB*TT];
__device__ float g_alignc[BB*TT];
__device__ float g_ctx[BB*HH];
__device__ float g_logits[(size_t)BB*VV];
__device__ float g_pm[BB*10];
__device__ float g_ps[BB*10];
__device__ float g_vred[BB*2];
__device__ float g_switch[BB];

__device__ __forceinline__ float sigf(float x){ return 1.0f/(1.0f+expf(-x)); }

__device__ __forceinline__ float tanh_fast(float x){
  float y;
  asm("tanh.approx.f32 %0, %1;" : "=f"(y) : "f"(x));
  return y;
}

// ---------------- init: biases / zeros into accumulators ----------------
#define INIT_TOTAL (117504 + 320000)
__global__ void init_kernel(const float* __restrict__ b1, const float* __restrict__ b2,
                            const float* __restrict__ bh, const float* __restrict__ bg) {
  int idx = blockIdx.x*blockDim.x + threadIdx.x;
  if (idx < 32768)            g_z1[idx] = b1[idx & 2047];
  else if (idx < 65536)       g_z2[idx-32768] = b2[idx & 2047];
  else if (idx < 81920)       g_q[idx-65536] = 0.f;
  else if (idx < 90112)       g_ha[idx-81920] = bh[idx & 511];
  else if (idx < 98304)       g_ctx[idx-90112] = 0.f;
  else if (idx < 107904)      g_sg[idx-98304] = 0.f;
  else if (idx < 117504)      g_sc[idx-107904] = 0.f;
  else if (idx < INIT_TOTAL) {
    int e = idx - 117504;
    g_logits[e] = bg[e % VV];
  }
}

// ---------------- convert enc_outs -> bf16 hi/lo ----------------
__global__ void convA_kernel(const float* __restrict__ A) {
  int i4 = blockIdx.x*blockDim.x + threadIdx.x;
  if (i4 >= BT*512/4) return;
  float4 v = *(const float4*)&A[i4*4];
  __nv_bfloat16 h0 = __float2bfloat16(v.x);
  __nv_bfloat16 h1 = __float2bfloat16(v.y);
  __nv_bfloat16 h2 = __float2bfloat16(v.z);
  __nv_bfloat16 h3 = __float2bfloat16(v.w);
  __nv_bfloat16 l0 = __float2bfloat16(v.x - __bfloat162float(h0));
  __nv_bfloat16 l1 = __float2bfloat16(v.y - __bfloat162float(h1));
  __nv_bfloat16 l2 = __float2bfloat16(v.z - __bfloat162float(h2));
  __nv_bfloat16 l3 = __float2bfloat16(v.w - __bfloat162float(h3));
  __nv_bfloat162* ph = (__nv_bfloat162*)g_A2h;
  __nv_bfloat162* pl = (__nv_bfloat162*)g_A2l;
  ph[i4*2]   = __nv_bfloat162(h0,h1);
  ph[i4*2+1] = __nv_bfloat162(h2,h3);
  pl[i4*2]   = __nv_bfloat162(l0,l1);
  pl[i4*2+1] = __nv_bfloat162(l2,l3);
}

// ---------------- transpose + convert W -> Wt bf16 hi/lo ----------------
__global__ void convW_kernel(const float* __restrict__ Wg, const float* __restrict__ Wc) {
  __shared__ float tile[32][33];
  int k0 = blockIdx.x*32;
  int n0 = blockIdx.y*32;
  const float* W = (n0 < 512) ? Wg : Wc;
  int nn0 = n0 & 511;
  int tx = threadIdx.x & 31, ty = threadIdx.x >> 5;
  #pragma unroll
  for (int i=0;i<4;i++) {
    int k = k0 + ty + i*8;
    tile[ty+i*8][tx] = W[(size_t)k*512 + nn0 + tx];
  }
  __syncthreads();
  __nv_bfloat16* WH = (__nv_bfloat16*)g_Wth;
  __nv_bfloat16* WL = (__nv_bfloat16*)g_Wtl;
  #pragma unroll
  for (int i=0;i<4;i++) {
    int n = n0 + ty + i*8;
    float x = tile[tx][ty+i*8];
    __nv_bfloat16 h = __float2bfloat16(x);
    WH[(size_t)n*512 + k0 + tx] = h;
    WL[(size_t)n*512 + k0 + tx] = __float2bfloat16(x - __bfloat162float(h));
  }
}

// ---------------- mma helpers ----------------
__device__ __forceinline__ void mma16816(float* c, const uint32_t* a, const uint32_t* b) {
  asm volatile(
    "mma.sync.aligned.m16n8k16.row.col.f32.bf16.bf16.f32 "
    "{%0,%1,%2,%3}, {%4,%5,%6,%7}, {%8,%9}, {%0,%1,%2,%3};"
    : "+f"(c[0]), "+f"(c[1]), "+f"(c[2]), "+f"(c[3])
    : "r"(a[0]), "r"(a[1]), "r"(a[2]), "r"(a[3]), "r"(b[0]), "r"(b[1]));
}

__device__ __forceinline__ void ldm_x4(uint32_t* r, uint32_t addr) {
  asm volatile("ldmatrix.sync.aligned.m8n8.x4.shared.b16 {%0,%1,%2,%3}, [%4];"
    : "=r"(r[0]), "=r"(r[1]), "=r"(r[2]), "=r"(r[3]) : "r"(addr));
}

// ---------------- fused: P = enc @ [aw2g|aw2c]; scores += tanh(q+P)*av ----------------
__global__ void __launch_bounds__(256, 2) mma_attn_scores_kernel(
    const float* __restrict__ avg, const float* __restrict__ avc) {
  __shared__ uint32_t sAh[128*20];
  __shared__ uint32_t sAl[128*20];
  __shared__ uint32_t sBh[128*20];
  __shared__ uint32_t sBl[128*20];
  __shared__ float s_av[128];
  __shared__ float s_q[2][128];

  int tid = threadIdx.x;
  int bm = blockIdx.x * 128;     // 75
  int bn = blockIdx.y * 128;     // 8
  int wid = tid >> 5, lane = tid & 31;
  int wm = wid >> 1, wn = wid & 1;
  int g = lane >> 2, t4 = lane & 3;

  int b_lo = bm / 600;
  int b_hi = (bm + 127) / 600;
  if (tid < 128) {
    const float* av = (bn < 512) ? avg : avc;
    s_av[tid] = av[(bn & 511) + tid];
    s_q[0][tid] = g_q[b_lo*1024 + bn + tid];
    s_q[1][tid] = g_q[b_hi*1024 + bn + tid];
  }

  uint32_t baseAh = (uint32_t)__cvta_generic_to_shared(sAh);
  uint32_t baseAl = (uint32_t)__cvta_generic_to_shared(sAl);
  uint32_t baseBh = (uint32_t)__cvta_generic_to_shared(sBh);
  uint32_t baseBl = (uint32_t)__cvta_generic_to_shared(sBl);
  uint32_t aoff = ((uint32_t)((wm*32 + (lane & 15))*20 + (lane >> 4)*4)) * 4;
  uint32_t aAh0 = baseAh + aoff, aAl0 = baseAl + aoff;
  uint32_t boff = ((uint32_t)((wn*64 + (lane & 7) + ((lane >> 4) << 3))*20 + ((lane >> 3) & 1)*4)) * 4;
  uint32_t bBh0 = baseBh + boff, bBl0 = baseBl + boff;

  float acc[2][8][4];
  #pragma unroll
  for (int mt=0;mt<2;mt++)
    #pragma unroll
    for (int nt=0;nt<8;nt++)
      #pragma unroll
      for (int r=0;r<4;r++) acc[mt][nt][r]=0.f;

  for (int kc=0; kc<512; kc+=32) {
    #pragma unroll
    for (int i=0;i<8;i++) {
      int e = tid + i*256;
      int row = e >> 4, kw = e & 15;
      size_t ga = (size_t)(bm+row)*256 + (kc>>1) + kw;
      size_t gb = (size_t)(bn+row)*256 + (kc>>1) + kw;
      int ss = row*20 + kw;
      sAh[ss] = g_A2h[ga];
      sAl[ss] = g_A2l[ga];
      sBh[ss] = g_Wth[gb];
      sBl[ss] = g_Wtl[gb];
    }
    __syncthreads();

    #pragma unroll
    for (int ks=0; ks<2; ks++) {
      uint32_t kb = ks*32;
      uint32_t ah[2][4], al[2][4];
      ldm_x4(ah[0], aAh0 + kb);
      ldm_x4(ah[1], aAh0 + 1280 + kb);
      ldm_x4(al[0], aAl0 + kb);
      ldm_x4(al[1], aAl0 + 1280 + kb);
      #pragma unroll
      for (int ntp=0; ntp<4; ntp++) {
        uint32_t bh4[4], bl4[4];
        ldm_x4(bh4, bBh0 + (uint32_t)ntp*1280 + kb);
        ldm_x4(bl4, bBl0 + (uint32_t)ntp*1280 + kb);
        int n0 = ntp*2, n1 = ntp*2+1;
        #pragma unroll
        for (int mt=0;mt<2;mt++) {
          mma16816(acc[mt][n0], ah[mt], bh4+0);
          mma16816(acc[mt][n0], ah[mt], bl4+0);
          mma16816(acc[mt][n0], al[mt], bh4+0);
          mma16816(acc[mt][n1], ah[mt], bh4+2);
          mma16816(acc[mt][n1], ah[mt], bl4+2);
          mma16816(acc[mt][n1], al[mt], bh4+2);
        }
      }
    }
    __syncthreads();
  }

  // fused scores epilogue with tanh.approx
  float* dst = (bn < 512) ? g_sg : g_sc;
  #pragma unroll
  for (int mt=0;mt<2;mt++) {
    #pragma unroll
    for (int rh=0; rh<2; rh++) {
      int row = bm + wm*32 + mt*16 + g + rh*8;
      int b = row / 600;
      int qs = (b == b_lo) ? 0 : 1;
      float s = 0.f;
      #pragma unroll
      for (int nt=0; nt<8; nt++) {
        int cl = wn*64 + nt*8 + t4*2;
        s += tanh_fast(s_q[qs][cl]   + acc[mt][nt][rh*2+0]) * s_av[cl];
        s += tanh_fast(s_q[qs][cl+1] + acc[mt][nt][rh*2+1]) * s_av[cl+1];
      }
      s += __shfl_xor_sync(0xffffffffu, s, 1);
      s += __shfl_xor_sync(0xffffffffu, s, 2);
      if (t4 == 0) atomicAdd(&dst[row], s);
    }
  }
}

// ---------------- small-M GEMM, batched float4 loads, K-split 32 + atomics ----------------
struct GArgs {
  const float* A0; const float* A1;
  const float* W0; const float* W1;
  const int* xidx; const float* emb;
  float* C;
  int K; int N;
};

enum { V_Z1=0, V_Z2=1, V_Q=2, V_HA=3 };

template<int VAR>
__device__ __forceinline__ float loadA(const GArgs& g, int b, int k) {
  if (VAR==V_Z1) {
    if (k < 300) return g.emb[(size_t)g.xidx[b]*300 + k];
    if (k < 812) return g.A0[b*512 + (k-300)];
    return g.A1[b*512 + (k-812)];
  }
  if (VAR==V_Z2 || VAR==V_HA) {
    if (k < 512) return g.A0[b*512+k];
    return g.A1[b*512 + (k-512)];
  }
  return g.A0[b*512+k]; // V_Q
}

// address-select form: SEL on pointer, single batchable LDG.128
template<int VAR>
__device__ __forceinline__ const float4* addrW4(const GArgs& g, int k, int c) {
  if (VAR==V_Z1) {
    const float* p = (k<812) ? (g.W0 + (size_t)k*2048) : (g.W1 + (size_t)(k-812)*2048);
    return (const float4*)(p + c);
  }
  if (VAR==V_Z2) {
    const float* p = (k<512) ? (g.W0 + (size_t)k*2048) : (g.W1 + (size_t)(k-512)*2048);
    return (const float4*)(p + c);
  }
  if (VAR==V_Q) {
    const float* p = (c<512) ? (g.W0 + (size_t)k*512 + c) : (g.W1 + (size_t)k*512 + (c-512));
    return (const float4*)p;
  }
  return (const float4*)(g.W0 + (size_t)k*512 + c); // V_HA
}

#define ACC4(bi, av) \
  acc[bi].x = fmaf(av, w.x, acc[bi].x); acc[bi].y = fmaf(av, w.y, acc[bi].y); \
  acc[bi].z = fmaf(av, w.z, acc[bi].z); acc[bi].w = fmaf(av, w.w, acc[bi].w);

// grid: (N/512, ceil(K/32)); block: 128. Four columns per thread, 32-deep K slice.
template<int VAR>
__global__ void gemm16_atomic(GArgs g) {
  __shared__ __align__(16) float As[32][16];
  int tid = threadIdx.x;                 // 128
  int col = blockIdx.x*512 + tid*4;
  int k0  = blockIdx.y*32;

  #pragma unroll
  for (int i=0;i<4;i++) {
    int e = tid + i*128;                 // 0..511
    int kl = e >> 4, b = e & 15;
    int k = k0 + kl;
    As[kl][b] = (k < g.K) ? loadA<VAR>(g, b, k) : 0.f;
  }
  __syncthreads();

  float4 acc[16];
  #pragma unroll
  for (int b=0;b<16;b++) acc[b] = make_float4(0.f,0.f,0.f,0.f);

  #pragma unroll
  for (int kb=0; kb<32; kb+=8) {
    float4 wb[8];
    #pragma unroll
    for (int j=0;j<8;j++) {
      int k = k0 + kb + j;
      wb[j] = (k < g.K) ? *addrW4<VAR>(g, k, col) : make_float4(0.f,0.f,0.f,0.f);
    }
    #pragma unroll
    for (int j=0;j<8;j++) {
      float4 w = wb[j];
      const float4* ap = (const float4*)&As[kb+j][0];
      float4 v0 = ap[0], v1 = ap[1], v2 = ap[2], v3 = ap[3];
      ACC4(0, v0.x)  ACC4(1, v0.y)  ACC4(2, v0.z)  ACC4(3, v0.w)
      ACC4(4, v1.x)  ACC4(5, v1.y)  ACC4(6, v1.z)  ACC4(7, v1.w)
      ACC4(8, v2.x)  ACC4(9, v2.y)  ACC4(10,v2.z)  ACC4(11,v2.w)
      ACC4(12,v3.x)  ACC4(13,v3.y)  ACC4(14,v3.z)  ACC4(15,v3.w)
    }
  }
  #pragma unroll
  for (int b=0;b<16;b++) {
    float* cp = &g.C[(size_t)b*g.N + col];
    atomicAdd(cp+0, acc[b].x); atomicAdd(cp+1, acc[b].y);
    atomicAdd(cp+2, acc[b].z); atomicAdd(cp+3, acc[b].w);
  }
}

// ---------------- logits: g_logits += ha @ Wg, batched loads, K-split 8x64 ----------------
__global__ void gemm16_logits_split(const float* __restrict__ A, const float* __restrict__ W) {
  __shared__ __align__(16) float As[64][16];
  int tid = threadIdx.x;                 // 128
  int col = blockIdx.x*512 + tid*4;
  int k0  = blockIdx.y*64;
  #pragma unroll
  for (int i=0;i<8;i++) {
    int e = tid + i*128;
    int kl = e >> 4, b = e & 15;
    As[kl][b] = A[b*512 + k0 + kl];
  }
  __syncthreads();
  if (col >= VV) return;
  float4 acc[16];
  #pragma unroll
  for (int b=0;b<16;b++) acc[b] = make_float4(0.f,0.f,0.f,0.f);

  #pragma unroll
  for (int kb=0; kb<64; kb+=8) {
    float4 wb[8];
    #pragma unroll
    for (int j=0;j<8;j++)
      wb[j] = *(const float4*)&W[(size_t)(k0+kb+j)*VV + col];
    #pragma unroll
    for (int j=0;j<8;j++) {
      float4 w = wb[j];
      const float4* ap = (const float4*)&As[kb+j][0];
      float4 v0 = ap[0], v1 = ap[1], v2 = ap[2], v3 = ap[3];
      ACC4(0, v0.x)  ACC4(1, v0.y)  ACC4(2, v0.z)  ACC4(3, v0.w)
      ACC4(4, v1.x)  ACC4(5, v1.y)  ACC4(6, v1.z)  ACC4(7, v1.w)
      ACC4(8, v2.x)  ACC4(9, v2.y)  ACC4(10,v2.z)  ACC4(11,v2.w)
      ACC4(12,v3.x)  ACC4(13,v3.y)  ACC4(14,v3.z)  ACC4(15,v3.w)
    }
  }
  #pragma unroll
  for (int b=0;b<16;b++) {
    float* cp = &g_logits[(size_t)b*VV + col];
    atomicAdd(cp+0, acc[b].x); atomicAdd(cp+1, acc[b].y);
    atomicAdd(cp+2, acc[b].z); atomicAdd(cp+3, acc[b].w);
  }
}

// ---------------- LSTM pointwise ----------------
__global__ void lstm_pw_kernel(const float* __restrict__ z, const float* __restrict__ cin,
                               float* __restrict__ hout, float* __restrict__ cout) {
  int idx = blockIdx.x*blockDim.x + threadIdx.x;
  if (idx >= BB*HH) return;
  int b = idx >> 9, j = idx & 511;
  const float* zb = z + b*2048;
  float iv = sigf(zb[j]);
  float fv = sigf(zb[512+j]);
  float gv = tanhf(zb[1024+j]);
  float ov = sigf(zb[1536+j]);
  float c = fv*cin[idx] + iv*gv;
  hout[idx] = ov*tanhf(c);
  cout[idx] = c;
}

// ---------------- softmax over T (both heads) ----------------
__global__ void softmax_kernel() {
  int b = blockIdx.x, tid = threadIdx.x;   // 256
  __shared__ float ag[TT], ac[TT];
  __shared__ float rbuf[256];
  for (int t=tid;t<TT;t+=256){ ag[t]=g_sg[b*TT+t]; ac[t]=g_sc[b*TT+t]; }
  __syncthreads();
  for (int pass=0; pass<2; pass++) {
    float* arr = pass ? ac : ag;
    float mx = -1e30f;
    for (int t=tid;t<TT;t+=256) mx = fmaxf(mx, arr[t]);
    rbuf[tid]=mx; __syncthreads();
    for (int s=128;s>0;s>>=1){ if (tid<s) rbuf[tid]=fmaxf(rbuf[tid],rbuf[tid+s]); __syncthreads(); }
    mx = rbuf[0]; __syncthreads();
    float ls=0.f;
    for (int t=tid;t<TT;t+=256){ float e=expf(arr[t]-mx); arr[t]=e; ls+=e; }
    rbuf[tid]=ls; __syncthreads();
    for (int s=128;s>0;s>>=1){ if (tid<s) rbuf[tid]+=rbuf[tid+s]; __syncthreads(); }
    float inv = 1.0f/rbuf[0]; __syncthreads();
    for (int t=tid;t<TT;t+=256) arr[t]*=inv;
    __syncthreads();
  }
  for (int t=tid;t<TT;t+=256){ g_aligng[b*TT+t]=ag[t]; g_alignc[b*TT+t]=ac[t]; }
}

// ---------------- context = align_g @ enc_outs, T-sliced + atomic ----------------
__global__ void ctx_kernel(const float* __restrict__ enc) {
  int s = blockIdx.x;            // 0..9
  int b = blockIdx.y;
  int tid = threadIdx.x;         // 512
  __shared__ float ag[60];
  if (tid < 60) ag[tid] = g_aligng[b*TT + s*60 + tid];
  __syncthreads();
  const float* eb = enc + (size_t)b*TT*HH + (size_t)(s*60)*HH + tid;
  float a0=0.f,a1=0.f,a2=0.f,a3=0.f,a4=0.f,a5=0.f;
  #pragma unroll 2
  for (int t=0;t<60;t+=6){
    a0 += ag[t]  *eb[(size_t)(t  )*HH];
    a1 += ag[t+1]*eb[(size_t)(t+1)*HH];
    a2 += ag[t+2]*eb[(size_t)(t+2)*HH];
    a3 += ag[t+3]*eb[(size_t)(t+3)*HH];
    a4 += ag[t+4]*eb[(size_t)(t+4)*HH];
    a5 += ag[t+5]*eb[(size_t)(t+5)*HH];
  }
  atomicAdd(&g_ctx[b*HH+tid], (a0+a1)+(a2+a3)+(a4+a5));
}

// ---------------- hidden_att finalize: tanh + switch ----------------
__global__ void ha_finalize_kernel(float* __restrict__ out_hidden,
                                   const float* __restrict__ Wf, const float* __restrict__ bf) {
  int b = blockIdx.x, tid = threadIdx.x;   // 512
  __shared__ float rb[512];
  float t = tanhf(g_ha[b*HH+tid]);
  out_hidden[b*HH+tid] = t;
  rb[tid] = t*Wf[tid];
  __syncthreads();
  for (int s=256;s>0;s>>=1){ if (tid<s) rb[tid]+=rb[tid+s]; __syncthreads(); }
  if (tid==0) g_switch[b] = sigf(rb[0]+bf[0]);
}

// ---------------- vocab softmax reductions, two-stage ----------------
__global__ void vred1_kernel() {
  int s = blockIdx.x, b = blockIdx.y;      // 10 x 16
  int tid = threadIdx.x;                   // 256
  __shared__ float rb[256];
  const float* lb = g_logits + (size_t)b*VV + s*2000;
  float mx = -1e30f;
  for (int i=tid;i<2000;i+=256) mx = fmaxf(mx, lb[i]);
  rb[tid]=mx; __syncthreads();
  for (int st=128;st>0;st>>=1){ if (tid<st) rb[tid]=fmaxf(rb[tid],rb[tid+st]); __syncthreads(); }
  mx = rb[0]; __syncthreads();
  float sm=0.f;
  for (int i=tid;i<2000;i+=256) sm += expf(lb[i]-mx);
  rb[tid]=sm; __syncthreads();
  for (int st=128;st>0;st>>=1){ if (tid<st) rb[tid]+=rb[tid+st]; __syncthreads(); }
  if (tid==0){ g_pm[b*10+s]=mx; g_ps[b*10+s]=rb[0]; }
}

__global__ void vred2_kernel() {
  int b = blockIdx.x, tid = threadIdx.x;   // 32
  float m = (tid<10) ? g_pm[b*10+tid] : -1e30f;
  #pragma unroll
  for (int o=16;o>0;o>>=1) m = fmaxf(m, __shfl_xor_sync(0xffffffffu, m, o));
  float s = (tid<10) ? g_ps[b*10+tid]*expf(g_pm[b*10+tid]-m) : 0.f;
  #pragma unroll
  for (int o=16;o>0;o>>=1) s += __shfl_xor_sync(0xffffffffu, s, o);
  if (tid==0){ g_vred[b*2]=m; g_vred[b*2+1]=s; }
}

// ---------------- copy pass: result <- copy_prob (768MB stream; overlaps logits chain) ----------------
__global__ void copy_kernel(const float* __restrict__ enc_ins, float* __restrict__ result) {
  int b = blockIdx.y, tid = threadIdx.x;   // 512
  int v = blockIdx.x*512 + tid;
  __shared__ float ac[TT];
  for (int t=tid;t<TT;t+=512) ac[t]=g_alignc[b*TT+t];
  __syncthreads();
  if (v >= VV) return;
  const float* eb = enc_ins + (size_t)b*TT*VV + v;
  float a0=0.f,a1=0.f,a2=0.f,a3=0.f,a4=0.f,a5=0.f,a6=0.f,a7=0.f;
  for (int t=0;t<TT;t+=8){
    a0 += ac[t]  * eb[(size_t)(t  )*VV];
    a1 += ac[t+1]* eb[(size_t)(t+1)*VV];
    a2 += ac[t+2]* eb[(size_t)(t+2)*VV];
    a3 += ac[t+3]* eb[(size_t)(t+3)*VV];
    a4 += ac[t+4]* eb[(size_t)(t+4)*VV];
    a5 += ac[t+5]* eb[(size_t)(t+5)*VV];
    a6 += ac[t+6]* eb[(size_t)(t+6)*VV];
    a7 += ac[t+7]* eb[(size_t)(t+7)*VV];
  }
  result[(size_t)b*VV+v] = ((a0+a1)+(a2+a3))+((a4+a5)+(a6+a7));
}

// ---------------- mix: result = gen*(1-sw) + copy*sw ----------------
__global__ void mix_kernel(float* __restrict__ result) {
  int b = blockIdx.y, tid = threadIdx.x;   // 512
  int v = blockIdx.x*512 + tid;
  if (v >= VV) return;
  float sw = g_switch[b];
  float mx = g_vred[b*2], sm = g_vred[b*2+1];
  float gen = expf(g_logits[(size_t)b*VV+v]-mx)/sm;
  size_t idx = (size_t)b*VV+v;
  result[idx] = gen*(1.0f-sw) + result[idx]*sw;
}

// ---------------- launch ----------------
extern "C" void kernel_launch(void* const* d_in, const int* in_sizes, int n_in,
                              void* d_out, int out_size) {
  const int*   x        = (const int*)  d_in[0];
  const float* lha      = (const float*)d_in[1];
  const float* h1       = (const float*)d_in[2];
  const float* c1       = (const float*)d_in[3];
  const float* h2       = (const float*)d_in[4];
  const float* c2       = (const float*)d_in[5];
  const float* enc_outs = (const float*)d_in[6];
  const float* enc_ins  = (const float*)d_in[7];
  const float* emb      = (const float*)d_in[8];
  const float* k1       = (const float*)d_in[9];
  const float* r1       = (const float*)d_in[10];
  const float* b1       = (const float*)d_in[11];
  const float* k2       = (const float*)d_in[12];
  const float* r2       = (const float*)d_in[13];
  const float* b2       = (const float*)d_in[14];
  const float* Wh       = (const float*)d_in[15];
  const float* bh       = (const float*)d_in[16];
  const float* Wg       = (const float*)d_in[17];
  const float* bg       = (const float*)d_in[18];
  const float* Wf       = (const float*)d_in[19];
  const float* bf       = (const float*)d_in[20];
  const float* aw1g     = (const float*)d_in[21];
  const float* aw2g     = (const float*)d_in[22];
  const float* avg      = (const float*)d_in[23];
  const float* aw1c     = (const float*)d_in[24];
  const float* aw2c     = (const float*)d_in[25];
  const float* avc      = (const float*)d_in[26];

  float* out = (float*)d_out;
  float* out_result = out;                       // 16*20000
  float* out_hidden = out + BB*VV;
  float* out_h1n    = out_hidden + BB*HH;
  float* out_c1n    = out_h1n + BB*HH;
  float* out_h2n    = out_c1n + BB*HH;
  float* out_c2n    = out_h2n + BB*HH;

  float *p_z1, *p_z2, *p_q, *p_ctx, *p_ha;
  cudaGetSymbolAddress((void**)&p_z1, g_z1);
  cudaGetSymbolAddress((void**)&p_z2, g_z2);
  cudaGetSymbolAddress((void**)&p_q, g_q);
  cudaGetSymbolAddress((void**)&p_ctx, g_ctx);
  cudaGetSymbolAddress((void**)&p_ha, g_ha);

  // side stream + fork/join events
  cudaStream_t s2;
  cudaStreamCreateWithFlags(&s2, cudaStreamNonBlocking);
  cudaEvent_t evFork, evJ1, evSoft, evCopy;
  cudaEventCreateWithFlags(&evFork, cudaEventDisableTiming);
  cudaEventCreateWithFlags(&evJ1, cudaEventDisableTiming);
  cudaEventCreateWithFlags(&evSoft, cudaEventDisableTiming);
  cudaEventCreateWithFlags(&evCopy, cudaEventDisableTiming);

  cudaEventRecord(evFork, 0);
  cudaStreamWaitEvent(s2, evFork, 0);

  // side stream: bf16 prep for the attention GEMM (overlaps LSTM chain)
  convA_kernel<<<(BT*512/4 + 255)/256, 256, 0, s2>>>(enc_outs);
  convW_kernel<<<dim3(16,32), 256, 0, s2>>>(aw2g, aw2c);
  cudaEventRecord(evJ1, s2);

  // main stream: init + LSTM chain
  init_kernel<<<(INIT_TOTAL+255)/256, 256>>>(b1, b2, bh, bg);

  GArgs az1; az1.A0=lha; az1.A1=h1; az1.W0=k1; az1.W1=r1;
  az1.xidx=x; az1.emb=emb; az1.C=p_z1; az1.K=1324; az1.N=2048;
  gemm16_atomic<V_Z1><<<dim3(4,42),128>>>(az1);
  lstm_pw_kernel<<<32,256>>>(p_z1, c1, out_h1n, out_c1n);

  GArgs az2; az2.A0=out_h1n; az2.A1=h2; az2.W0=k2; az2.W1=r2;
  az2.xidx=nullptr; az2.emb=nullptr; az2.C=p_z2; az2.K=1024; az2.N=2048;
  gemm16_atomic<V_Z2><<<dim3(4,32),128>>>(az2);
  lstm_pw_kernel<<<32,256>>>(p_z2, c2, out_h2n, out_c2n);

  GArgs aq; aq.A0=out_h2n; aq.A1=nullptr; aq.W0=aw1g; aq.W1=aw1c;
  aq.xidx=nullptr; aq.emb=nullptr; aq.C=p_q; aq.K=512; aq.N=1024;
  gemm16_atomic<V_Q><<<dim3(2,16),128>>>(aq);

  // join 1: need bf16 enc/W for mma
  cudaStreamWaitEvent(0, evJ1, 0);
  mma_attn_scores_kernel<<<dim3(75,8), 256>>>(avg, avc);

  softmax_kernel<<<BB,256>>>();
  cudaEventRecord(evSoft, 0);

  // side stream: big copy pass as soon as align_c is ready
  cudaStreamWaitEvent(s2, evSoft, 0);
  copy_kernel<<<dim3((VV+511)/512, BB), 512, 0, s2>>>(enc_ins, out_result);
  cudaEventRecord(evCopy, s2);

  // main stream: gen-prob chain (overlaps the copy stream)
  ctx_kernel<<<dim3(10,BB),512>>>(enc_outs);

  GArgs aha; aha.A0=p_ctx; aha.A1=out_h2n; aha.W0=Wh; aha.W1=nullptr;
  aha.xidx=nullptr; aha.emb=nullptr; aha.C=p_ha; aha.K=1024; aha.N=512;
  gemm16_atomic<V_HA><<<dim3(1,32),128>>>(aha);
  ha_finalize_kernel<<<BB,512>>>(out_hidden, Wf, bf);

  gemm16_logits_split<<<dim3(40,8),128>>>(out_hidden, Wg);
  vred1_kernel<<<dim3(10,BB),256>>>();
  vred2_kernel<<<BB,32>>>();

  // join 2: copy must be in result before mixing
  cudaStreamWaitEvent(0, evCopy, 0);
  mix_kernel<<<dim3((VV+511)/512, BB), 512>>>(out_result);
}

// round 13
// speedup vs baseline: 1.5975x; 1.0432x over previous
#include <cuda_runtime.h>
#include <cuda_bf16.h>
#include <math.h>
#include <stdint.h>

#define BB 16
#define TT 600
#define VV 20000
#define EE 300
#define HH 512
#define BT (BB*TT)   // 9600

// ---------------- scratch ----------------
__device__ uint32_t g_A2h[(size_t)BT*256];   // enc hi, bf16 [9600][512] packed as u32
__device__ uint32_t g_A2l[(size_t)BT*256];   // enc lo
__device__ uint32_t g_Wth[1024*256];         // W^T hi, bf16 [1024 n][512 k]
__device__ uint32_t g_Wtl[1024*256];         // W^T lo
__device__ float g_z1[BB*2048];
__device__ float g_z2[BB*2048];
__device__ float g_q[BB*1024];
__device__ float g_ha[BB*HH];
__device__ float g_sg[BB*TT];
__device__ float g_sc[BB*TT];
__device__ float g_aligng[BB*TT];
__device__ float g_alignc[BB*TT];
__device__ float g_ctx[BB*HH];
__device__ float g_logits[(size_t)BB*VV];
__device__ float g_pm[BB*10];
__device__ float g_ps[BB*10];
__device__ float g_vred[BB*2];
__device__ float g_switch[BB];

__device__ __forceinline__ float sigf(float x){ return 1.0f/(1.0f+expf(-x)); }

__device__ __forceinline__ float tanh_fast(float x){
  float y;
  asm("tanh.approx.f32 %0, %1;" : "=f"(y) : "f"(x));
  return y;
}

// ---------------- init: biases / zeros into accumulators ----------------
#define INIT_TOTAL (117504 + 320000)
__global__ void init_kernel(const float* __restrict__ b1, const float* __restrict__ b2,
                            const float* __restrict__ bh, const float* __restrict__ bg) {
  int idx = blockIdx.x*blockDim.x + threadIdx.x;
  if (idx < 32768)            g_z1[idx] = b1[idx & 2047];
  else if (idx < 65536)       g_z2[idx-32768] = b2[idx & 2047];
  else if (idx < 81920)       g_q[idx-65536] = 0.f;
  else if (idx < 90112)       g_ha[idx-81920] = bh[idx & 511];
  else if (idx < 98304)       g_ctx[idx-90112] = 0.f;
  else if (idx < 107904)      g_sg[idx-98304] = 0.f;
  else if (idx < 117504)      g_sc[idx-107904] = 0.f;
  else if (idx < INIT_TOTAL) {
    int e = idx - 117504;
    g_logits[e] = bg[e % VV];
  }
}

// ---------------- convert enc_outs -> bf16 hi/lo ----------------
__global__ void convA_kernel(const float* __restrict__ A) {
  int i4 = blockIdx.x*blockDim.x + threadIdx.x;
  if (i4 >= BT*512/4) return;
  float4 v = *(const float4*)&A[i4*4];
  __nv_bfloat16 h0 = __float2bfloat16(v.x);
  __nv_bfloat16 h1 = __float2bfloat16(v.y);
  __nv_bfloat16 h2 = __float2bfloat16(v.z);
  __nv_bfloat16 h3 = __float2bfloat16(v.w);
  __nv_bfloat16 l0 = __float2bfloat16(v.x - __bfloat162float(h0));
  __nv_bfloat16 l1 = __float2bfloat16(v.y - __bfloat162float(h1));
  __nv_bfloat16 l2 = __float2bfloat16(v.z - __bfloat162float(h2));
  __nv_bfloat16 l3 = __float2bfloat16(v.w - __bfloat162float(h3));
  __nv_bfloat162* ph = (__nv_bfloat162*)g_A2h;
  __nv_bfloat162* pl = (__nv_bfloat162*)g_A2l;
  ph[i4*2]   = __nv_bfloat162(h0,h1);
  ph[i4*2+1] = __nv_bfloat162(h2,h3);
  pl[i4*2]   = __nv_bfloat162(l0,l1);
  pl[i4*2+1] = __nv_bfloat162(l2,l3);
}

// ---------------- transpose + convert W -> Wt bf16 hi/lo ----------------
__global__ void convW_kernel(const float* __restrict__ Wg, const float* __restrict__ Wc) {
  __shared__ float tile[32][33];
  int k0 = blockIdx.x*32;
  int n0 = blockIdx.y*32;
  const float* W = (n0 < 512) ? Wg : Wc;
  int nn0 = n0 & 511;
  int tx = threadIdx.x & 31, ty = threadIdx.x >> 5;
  #pragma unroll
  for (int i=0;i<4;i++) {
    int k = k0 + ty + i*8;
    tile[ty+i*8][tx] = W[(size_t)k*512 + nn0 + tx];
  }
  __syncthreads();
  __nv_bfloat16* WH = (__nv_bfloat16*)g_Wth;
  __nv_bfloat16* WL = (__nv_bfloat16*)g_Wtl;
  #pragma unroll
  for (int i=0;i<4;i++) {
    int n = n0 + ty + i*8;
    float x = tile[tx][ty+i*8];
    __nv_bfloat16 h = __float2bfloat16(x);
    WH[(size_t)n*512 + k0 + tx] = h;
    WL[(size_t)n*512 + k0 + tx] = __float2bfloat16(x - __bfloat162float(h));
  }
}

// ---------------- mma helpers ----------------
__device__ __forceinline__ void mma16816(float* c, const uint32_t* a, const uint32_t* b) {
  asm volatile(
    "mma.sync.aligned.m16n8k16.row.col.f32.bf16.bf16.f32 "
    "{%0,%1,%2,%3}, {%4,%5,%6,%7}, {%8,%9}, {%0,%1,%2,%3};"
    : "+f"(c[0]), "+f"(c[1]), "+f"(c[2]), "+f"(c[3])
    : "r"(a[0]), "r"(a[1]), "r"(a[2]), "r"(a[3]), "r"(b[0]), "r"(b[1]));
}

__device__ __forceinline__ void ldm_x4(uint32_t* r, uint32_t addr) {
  asm volatile("ldmatrix.sync.aligned.m8n8.x4.shared.b16 {%0,%1,%2,%3}, [%4];"
    : "=r"(r[0]), "=r"(r[1]), "=r"(r[2]), "=r"(r[3]) : "r"(addr));
}

// ---------------- fused: P = enc @ [aw2g|aw2c]; scores += tanh(q+P)*av ----------------
__global__ void __launch_bounds__(256, 2) mma_attn_scores_kernel(
    const float* __restrict__ avg, const float* __restrict__ avc) {
  __shared__ uint32_t sAh[128*20];
  __shared__ uint32_t sAl[128*20];
  __shared__ uint32_t sBh[128*20];
  __shared__ uint32_t sBl[128*20];
  __shared__ float s_av[128];
  __shared__ float s_q[2][128];

  int tid = threadIdx.x;
  int bm = blockIdx.x * 128;     // 75
  int bn = blockIdx.y * 128;     // 8
  int wid = tid >> 5, lane = tid & 31;
  int wm = wid >> 1, wn = wid & 1;
  int g = lane >> 2, t4 = lane & 3;

  int b_lo = bm / 600;
  int b_hi = (bm + 127) / 600;
  if (tid < 128) {
    const float* av = (bn < 512) ? avg : avc;
    s_av[tid] = av[(bn & 511) + tid];
    s_q[0][tid] = g_q[b_lo*1024 + bn + tid];
    s_q[1][tid] = g_q[b_hi*1024 + bn + tid];
  }

  uint32_t baseAh = (uint32_t)__cvta_generic_to_shared(sAh);
  uint32_t baseAl = (uint32_t)__cvta_generic_to_shared(sAl);
  uint32_t baseBh = (uint32_t)__cvta_generic_to_shared(sBh);
  uint32_t baseBl = (uint32_t)__cvta_generic_to_shared(sBl);
  uint32_t aoff = ((uint32_t)((wm*32 + (lane & 15))*20 + (lane >> 4)*4)) * 4;
  uint32_t aAh0 = baseAh + aoff, aAl0 = baseAl + aoff;
  uint32_t boff = ((uint32_t)((wn*64 + (lane & 7) + ((lane >> 4) << 3))*20 + ((lane >> 3) & 1)*4)) * 4;
  uint32_t bBh0 = baseBh + boff, bBl0 = baseBl + boff;

  float acc[2][8][4];
  #pragma unroll
  for (int mt=0;mt<2;mt++)
    #pragma unroll
    for (int nt=0;nt<8;nt++)
      #pragma unroll
      for (int r=0;r<4;r++) acc[mt][nt][r]=0.f;

  for (int kc=0; kc<512; kc+=32) {
    // vectorized staging: 512 uint4 per array, 2 per thread per array
    #pragma unroll
    for (int i=0;i<2;i++) {
      int e = tid + i*256;          // 0..511 uint4 index
      int row = e >> 2;             // 0..127
      int q4  = e & 3;              // which 16B within the 64B k-slice
      size_t ga = (size_t)(bm+row)*64 + (kc>>3) + q4;   // uint4 units (row stride 64)
      size_t gb = (size_t)(bn+row)*64 + (kc>>3) + q4;
      int ss4 = row*5 + q4;         // smem uint4 index (row stride 20 u32 = 5 uint4)
      ((uint4*)sAh)[ss4] = ((const uint4*)g_A2h)[ga];
      ((uint4*)sAl)[ss4] = ((const uint4*)g_A2l)[ga];
      ((uint4*)sBh)[ss4] = ((const uint4*)g_Wth)[gb];
      ((uint4*)sBl)[ss4] = ((const uint4*)g_Wtl)[gb];
    }
    __syncthreads();

    #pragma unroll
    for (int ks=0; ks<2; ks++) {
      uint32_t kb = ks*32;
      uint32_t ah[2][4], al[2][4];
      ldm_x4(ah[0], aAh0 + kb);
      ldm_x4(ah[1], aAh0 + 1280 + kb);
      ldm_x4(al[0], aAl0 + kb);
      ldm_x4(al[1], aAl0 + 1280 + kb);
      #pragma unroll
      for (int ntp=0; ntp<4; ntp++) {
        uint32_t bh4[4], bl4[4];
        ldm_x4(bh4, bBh0 + (uint32_t)ntp*1280 + kb);
        ldm_x4(bl4, bBl0 + (uint32_t)ntp*1280 + kb);
        int n0 = ntp*2, n1 = ntp*2+1;
        #pragma unroll
        for (int mt=0;mt<2;mt++) {
          mma16816(acc[mt][n0], ah[mt], bh4+0);
          mma16816(acc[mt][n0], ah[mt], bl4+0);
          mma16816(acc[mt][n0], al[mt], bh4+0);
          mma16816(acc[mt][n1], ah[mt], bh4+2);
          mma16816(acc[mt][n1], ah[mt], bl4+2);
          mma16816(acc[mt][n1], al[mt], bh4+2);
        }
      }
    }
    __syncthreads();
  }

  // fused scores epilogue with tanh.approx
  float* dst = (bn < 512) ? g_sg : g_sc;
  #pragma unroll
  for (int mt=0;mt<2;mt++) {
    #pragma unroll
    for (int rh=0; rh<2; rh++) {
      int row = bm + wm*32 + mt*16 + g + rh*8;
      int b = row / 600;
      int qs = (b == b_lo) ? 0 : 1;
      float s = 0.f;
      #pragma unroll
      for (int nt=0; nt<8; nt++) {
        int cl = wn*64 + nt*8 + t4*2;
        s += tanh_fast(s_q[qs][cl]   + acc[mt][nt][rh*2+0]) * s_av[cl];
        s += tanh_fast(s_q[qs][cl+1] + acc[mt][nt][rh*2+1]) * s_av[cl+1];
      }
      s += __shfl_xor_sync(0xffffffffu, s, 1);
      s += __shfl_xor_sync(0xffffffffu, s, 2);
      if (t4 == 0) atomicAdd(&dst[row], s);
    }
  }
}

// ---------------- small-M GEMM, batched float4 loads, K-split 32 + atomics ----------------
struct GArgs {
  const float* A0; const float* A1;
  const float* W0; const float* W1;
  const int* xidx; const float* emb;   // emb doubles as c-state pointer for inline LSTM
  float* C;
  int K; int N;
};

enum { V_Z1=0, V_Z2=1, V_Q=2, V_HA=3 };

// inline LSTM hidden-state from pre-activation z and cell c
__device__ __forceinline__ float lstm_h(const float* zb, const float* cb, int b, int j) {
  float iv = sigf(zb[j]);
  float fv = sigf(zb[512+j]);
  float gv = tanhf(zb[1024+j]);
  float ov = sigf(zb[1536+j]);
  float c = fv*cb[b*512+j] + iv*gv;
  return ov*tanhf(c);
}

template<int VAR>
__device__ __forceinline__ float loadA(const GArgs& g, int b, int k) {
  if (VAR==V_Z1) {
    if (k < 300) return g.emb[(size_t)g.xidx[b]*300 + k];
    if (k < 812) return g.A0[b*512 + (k-300)];
    return g.A1[b*512 + (k-812)];
  }
  if (VAR==V_Z2) {
    // A0 = g_z1, emb = c1, A1 = h2(old)
    if (k < 512) return lstm_h(g.A0 + b*2048, g.emb, b, k);
    return g.A1[b*512 + (k-512)];
  }
  if (VAR==V_HA) {
    if (k < 512) return g.A0[b*512+k];
    return g.A1[b*512 + (k-512)];
  }
  // V_Q: A0 = g_z2, emb = c2
  return lstm_h(g.A0 + b*2048, g.emb, b, k);
}

// address-select form: SEL on pointer, single batchable LDG.128
template<int VAR>
__device__ __forceinline__ const float4* addrW4(const GArgs& g, int k, int c) {
  if (VAR==V_Z1) {
    const float* p = (k<812) ? (g.W0 + (size_t)k*2048) : (g.W1 + (size_t)(k-812)*2048);
    return (const float4*)(p + c);
  }
  if (VAR==V_Z2) {
    const float* p = (k<512) ? (g.W0 + (size_t)k*2048) : (g.W1 + (size_t)(k-512)*2048);
    return (const float4*)(p + c);
  }
  if (VAR==V_Q) {
    const float* p = (c<512) ? (g.W0 + (size_t)k*512 + c) : (g.W1 + (size_t)k*512 + (c-512));
    return (const float4*)p;
  }
  return (const float4*)(g.W0 + (size_t)k*512 + c); // V_HA
}

#define ACC4(bi, av) \
  acc[bi].x = fmaf(av, w.x, acc[bi].x); acc[bi].y = fmaf(av, w.y, acc[bi].y); \
  acc[bi].z = fmaf(av, w.z, acc[bi].z); acc[bi].w = fmaf(av, w.w, acc[bi].w);

// grid: (N/512, ceil(K/32)); block: 128. Four columns per thread, 32-deep K slice.
// 4-deep load batch (8 spilled at regs=127; 4 fits under 112).
template<int VAR>
__global__ void gemm16_atomic(GArgs g) {
  __shared__ __align__(16) float As[32][16];
  int tid = threadIdx.x;                 // 128
  int col = blockIdx.x*512 + tid*4;
  int k0  = blockIdx.y*32;

  #pragma unroll
  for (int i=0;i<4;i++) {
    int e = tid + i*128;                 // 0..511
    int kl = e >> 4, b = e & 15;
    int k = k0 + kl;
    As[kl][b] = (k < g.K) ? loadA<VAR>(g, b, k) : 0.f;
  }
  __syncthreads();

  float4 acc[16];
  #pragma unroll
  for (int b=0;b<16;b++) acc[b] = make_float4(0.f,0.f,0.f,0.f);

  #pragma unroll
  for (int kb=0; kb<32; kb+=4) {
    float4 wb[4];
    #pragma unroll
    for (int j=0;j<4;j++) {
      int k = k0 + kb + j;
      wb[j] = (k < g.K) ? *addrW4<VAR>(g, k, col) : make_float4(0.f,0.f,0.f,0.f);
    }
    #pragma unroll
    for (int j=0;j<4;j++) {
      float4 w = wb[j];
      const float4* ap = (const float4*)&As[kb+j][0];
      float4 v0 = ap[0], v1 = ap[1], v2 = ap[2], v3 = ap[3];
      ACC4(0, v0.x)  ACC4(1, v0.y)  ACC4(2, v0.z)  ACC4(3, v0.w)
      ACC4(4, v1.x)  ACC4(5, v1.y)  ACC4(6, v1.z)  ACC4(7, v1.w)
      ACC4(8, v2.x)  ACC4(9, v2.y)  ACC4(10,v2.z)  ACC4(11,v2.w)
      ACC4(12,v3.x)  ACC4(13,v3.y)  ACC4(14,v3.z)  ACC4(15,v3.w)
    }
  }
  #pragma unroll
  for (int b=0;b<16;b++) {
    float* cp = &g.C[(size_t)b*g.N + col];
    atomicAdd(cp+0, acc[b].x); atomicAdd(cp+1, acc[b].y);
    atomicAdd(cp+2, acc[b].z); atomicAdd(cp+3, acc[b].w);
  }
}

// ---------------- logits: g_logits += ha @ Wg, batched loads, K-split 8x64 ----------------
__global__ void gemm16_logits_split(const float* __restrict__ A, const float* __restrict__ W) {
  __shared__ __align__(16) float As[64][16];
  int tid = threadIdx.x;                 // 128
  int col = blockIdx.x*512 + tid*4;
  int k0  = blockIdx.y*64;
  #pragma unroll
  for (int i=0;i<8;i++) {
    int e = tid + i*128;
    int kl = e >> 4, b = e & 15;
    As[kl][b] = A[b*512 + k0 + kl];
  }
  __syncthreads();
  if (col >= VV) return;
  float4 acc[16];
  #pragma unroll
  for (int b=0;b<16;b++) acc[b] = make_float4(0.f,0.f,0.f,0.f);

  #pragma unroll
  for (int kb=0; kb<64; kb+=4) {
    float4 wb[4];
    #pragma unroll
    for (int j=0;j<4;j++)
      wb[j] = *(const float4*)&W[(size_t)(k0+kb+j)*VV + col];
    #pragma unroll
    for (int j=0;j<4;j++) {
      float4 w = wb[j];
      const float4* ap = (const float4*)&As[kb+j][0];
      float4 v0 = ap[0], v1 = ap[1], v2 = ap[2], v3 = ap[3];
      ACC4(0, v0.x)  ACC4(1, v0.y)  ACC4(2, v0.z)  ACC4(3, v0.w)
      ACC4(4, v1.x)  ACC4(5, v1.y)  ACC4(6, v1.z)  ACC4(7, v1.w)
      ACC4(8, v2.x)  ACC4(9, v2.y)  ACC4(10,v2.z)  ACC4(11,v2.w)
      ACC4(12,v3.x)  ACC4(13,v3.y)  ACC4(14,v3.z)  ACC4(15,v3.w)
    }
  }
  #pragma unroll
  for (int b=0;b<16;b++) {
    float* cp = &g_logits[(size_t)b*VV + col];
    atomicAdd(cp+0, acc[b].x); atomicAdd(cp+1, acc[b].y);
    atomicAdd(cp+2, acc[b].z); atomicAdd(cp+3, acc[b].w);
  }
}

// ---------------- LSTM pointwise (off critical path; produces h/c outputs) ----------------
__global__ void lstm_pw_kernel(const float* __restrict__ z, const float* __restrict__ cin,
                               float* __restrict__ hout, float* __restrict__ cout) {
  int idx = blockIdx.x*blockDim.x + threadIdx.x;
  if (idx >= BB*HH) return;
  int b = idx >> 9, j = idx & 511;
  const float* zb = z + b*2048;
  float iv = sigf(zb[j]);
  float fv = sigf(zb[512+j]);
  float gv = tanhf(zb[1024+j]);
  float ov = sigf(zb[1536+j]);
  float c = fv*cin[idx] + iv*gv;
  hout[idx] = ov*tanhf(c);
  cout[idx] = c;
}

// ---------------- softmax over T (both heads) ----------------
__global__ void softmax_kernel() {
  int b = blockIdx.x, tid = threadIdx.x;   // 256
  __shared__ float ag[TT], ac[TT];
  __shared__ float rbuf[256];
  for (int t=tid;t<TT;t+=256){ ag[t]=g_sg[b*TT+t]; ac[t]=g_sc[b*TT+t]; }
  __syncthreads();
  for (int pass=0; pass<2; pass++) {
    float* arr = pass ? ac : ag;
    float mx = -1e30f;
    for (int t=tid;t<TT;t+=256) mx = fmaxf(mx, arr[t]);
    rbuf[tid]=mx; __syncthreads();
    for (int s=128;s>0;s>>=1){ if (tid<s) rbuf[tid]=fmaxf(rbuf[tid],rbuf[tid+s]); __syncthreads(); }
    mx = rbuf[0]; __syncthreads();
    float ls=0.f;
    for (int t=tid;t<TT;t+=256){ float e=expf(arr[t]-mx); arr[t]=e; ls+=e; }
    rbuf[tid]=ls; __syncthreads();
    for (int s=128;s>0;s>>=1){ if (tid<s) rbuf[tid]+=rbuf[tid+s]; __syncthreads(); }
    float inv = 1.0f/rbuf[0]; __syncthreads();
    for (int t=tid;t<TT;t+=256) arr[t]*=inv;
    __syncthreads();
  }
  for (int t=tid;t<TT;t+=256){ g_aligng[b*TT+t]=ag[t]; g_alignc[b*TT+t]=ac[t]; }
}

// ---------------- context = align_g @ enc_outs, T-sliced + atomic ----------------
__global__ void ctx_kernel(const float* __restrict__ enc) {
  int s = blockIdx.x;            // 0..9
  int b = blockIdx.y;
  int tid = threadIdx.x;         // 512
  __shared__ float ag[60];
  if (tid < 60) ag[tid] = g_aligng[b*TT + s*60 + tid];
  __syncthreads();
  const float* eb = enc + (size_t)b*TT*HH + (size_t)(s*60)*HH + tid;
  float a0=0.f,a1=0.f,a2=0.f,a3=0.f,a4=0.f,a5=0.f;
  #pragma unroll 2
  for (int t=0;t<60;t+=6){
    a0 += ag[t]  *eb[(size_t)(t  )*HH];
    a1 += ag[t+1]*eb[(size_t)(t+1)*HH];
    a2 += ag[t+2]*eb[(size_t)(t+2)*HH];
    a3 += ag[t+3]*eb[(size_t)(t+3)*HH];
    a4 += ag[t+4]*eb[(size_t)(t+4)*HH];
    a5 += ag[t+5]*eb[(size_t)(t+5)*HH];
  }
  atomicAdd(&g_ctx[b*HH+tid], (a0+a1)+(a2+a3)+(a4+a5));
}

// ---------------- hidden_att finalize: tanh + switch ----------------
__global__ void ha_finalize_kernel(float* __restrict__ out_hidden,
                                   const float* __restrict__ Wf, const float* __restrict__ bf) {
  int b = blockIdx.x, tid = threadIdx.x;   // 512
  __shared__ float rb[512];
  float t = tanhf(g_ha[b*HH+tid]);
  out_hidden[b*HH+tid] = t;
  rb[tid] = t*Wf[tid];
  __syncthreads();
  for (int s=256;s>0;s>>=1){ if (tid<s) rb[tid]+=rb[tid+s]; __syncthreads(); }
  if (tid==0) g_switch[b] = sigf(rb[0]+bf[0]);
}

// ---------------- vocab softmax reductions, two-stage ----------------
__global__ void vred1_kernel() {
  int s = blockIdx.x, b = blockIdx.y;      // 10 x 16
  int tid = threadIdx.x;                   // 256
  __shared__ float rb[256];
  const float* lb = g_logits + (size_t)b*VV + s*2000;
  float mx = -1e30f;
  for (int i=tid;i<2000;i+=256) mx = fmaxf(mx, lb[i]);
  rb[tid]=mx; __syncthreads();
  for (int st=128;st>0;st>>=1){ if (tid<st) rb[tid]=fmaxf(rb[tid],rb[tid+st]); __syncthreads(); }
  mx = rb[0]; __syncthreads();
  float sm=0.f;
  for (int i=tid;i<2000;i+=256) sm += expf(lb[i]-mx);
  rb[tid]=sm; __syncthreads();
  for (int st=128;st>0;st>>=1){ if (tid<st) rb[tid]+=rb[tid+st]; __syncthreads(); }
  if (tid==0){ g_pm[b*10+s]=mx; g_ps[b*10+s]=rb[0]; }
}

__global__ void vred2_kernel() {
  int b = blockIdx.x, tid = threadIdx.x;   // 32
  float m = (tid<10) ? g_pm[b*10+tid] : -1e30f;
  #pragma unroll
  for (int o=16;o>0;o>>=1) m = fmaxf(m, __shfl_xor_sync(0xffffffffu, m, o));
  float s = (tid<10) ? g_ps[b*10+tid]*expf(g_pm[b*10+tid]-m) : 0.f;
  #pragma unroll
  for (int o=16;o>0;o>>=1) s += __shfl_xor_sync(0xffffffffu, s, o);
  if (tid==0){ g_vred[b*2]=m; g_vred[b*2+1]=s; }
}

// ---------------- copy pass: result <- copy_prob (768MB stream; overlaps logits chain) ----------------
__global__ void copy_kernel(const float* __restrict__ enc_ins, float* __restrict__ result) {
  int b = blockIdx.y, tid = threadIdx.x;   // 512
  int v = blockIdx.x*512 + tid;
  __shared__ float ac[TT];
  for (int t=tid;t<TT;t+=512) ac[t]=g_alignc[b*TT+t];
  __syncthreads();
  if (v >= VV) return;
  const float* eb = enc_ins + (size_t)b*TT*VV + v;
  float a0=0.f,a1=0.f,a2=0.f,a3=0.f,a4=0.f,a5=0.f,a6=0.f,a7=0.f;
  for (int t=0;t<TT;t+=8){
    a0 += ac[t]  * eb[(size_t)(t  )*VV];
    a1 += ac[t+1]* eb[(size_t)(t+1)*VV];
    a2 += ac[t+2]* eb[(size_t)(t+2)*VV];
    a3 += ac[t+3]* eb[(size_t)(t+3)*VV];
    a4 += ac[t+4]* eb[(size_t)(t+4)*VV];
    a5 += ac[t+5]* eb[(size_t)(t+5)*VV];
    a6 += ac[t+6]* eb[(size_t)(t+6)*VV];
    a7 += ac[t+7]* eb[(size_t)(t+7)*VV];
  }
  result[(size_t)b*VV+v] = ((a0+a1)+(a2+a3))+((a4+a5)+(a6+a7));
}

// ---------------- mix: result = gen*(1-sw) + copy*sw ----------------
__global__ void mix_kernel(float* __restrict__ result) {
  int b = blockIdx.y, tid = threadIdx.x;   // 512
  int v = blockIdx.x*512 + tid;
  if (v >= VV) return;
  float sw = g_switch[b];
  float mx = g_vred[b*2], sm = g_vred[b*2+1];
  float gen = expf(g_logits[(size_t)b*VV+v]-mx)/sm;
  size_t idx = (size_t)b*VV+v;
  result[idx] = gen*(1.0f-sw) + result[idx]*sw;
}

// ---------------- launch ----------------
extern "C" void kernel_launch(void* const* d_in, const int* in_sizes, int n_in,
                              void* d_out, int out_size) {
  const int*   x        = (const int*)  d_in[0];
  const float* lha      = (const float*)d_in[1];
  const float* h1       = (const float*)d_in[2];
  const float* c1       = (const float*)d_in[3];
  const float* h2       = (const float*)d_in[4];
  const float* c2       = (const float*)d_in[5];
  const float* enc_outs = (const float*)d_in[6];
  const float* enc_ins  = (const float*)d_in[7];
  const float* emb      = (const float*)d_in[8];
  const float* k1       = (const float*)d_in[9];
  const float* r1       = (const float*)d_in[10];
  const float* b1       = (const float*)d_in[11];
  const float* k2       = (const float*)d_in[12];
  const float* r2       = (const float*)d_in[13];
  const float* b2       = (const float*)d_in[14];
  const float* Wh       = (const float*)d_in[15];
  const float* bh       = (const float*)d_in[16];
  const float* Wg       = (const float*)d_in[17];
  const float* bg       = (const float*)d_in[18];
  const float* Wf       = (const float*)d_in[19];
  const float* bf       = (const float*)d_in[20];
  const float* aw1g     = (const float*)d_in[21];
  const float* aw2g     = (const float*)d_in[22];
  const float* avg      = (const float*)d_in[23];
  const float* aw1c     = (const float*)d_in[24];
  const float* aw2c     = (const float*)d_in[25];
  const float* avc      = (const float*)d_in[26];

  float* out = (float*)d_out;
  float* out_result = out;                       // 16*20000
  float* out_hidden = out + BB*VV;
  float* out_h1n    = out_hidden + BB*HH;
  float* out_c1n    = out_h1n + BB*HH;
  float* out_h2n    = out_c1n + BB*HH;
  float* out_c2n    = out_h2n + BB*HH;

  float *p_z1, *p_z2, *p_q, *p_ctx, *p_ha;
  cudaGetSymbolAddress((void**)&p_z1, g_z1);
  cudaGetSymbolAddress((void**)&p_z2, g_z2);
  cudaGetSymbolAddress((void**)&p_q, g_q);
  cudaGetSymbolAddress((void**)&p_ctx, g_ctx);
  cudaGetSymbolAddress((void**)&p_ha, g_ha);

  // side stream + fork/join events
  cudaStream_t s2;
  cudaStreamCreateWithFlags(&s2, cudaStreamNonBlocking);
  cudaEvent_t evFork, evJ1, evZ1, evZ2, evPW2, evSoft, evCopy;
  cudaEventCreateWithFlags(&evFork, cudaEventDisableTiming);
  cudaEventCreateWithFlags(&evJ1, cudaEventDisableTiming);
  cudaEventCreateWithFlags(&evZ1, cudaEventDisableTiming);
  cudaEventCreateWithFlags(&evZ2, cudaEventDisableTiming);
  cudaEventCreateWithFlags(&evPW2, cudaEventDisableTiming);
  cudaEventCreateWithFlags(&evSoft, cudaEventDisableTiming);
  cudaEventCreateWithFlags(&evCopy, cudaEventDisableTiming);

  cudaEventRecord(evFork, 0);
  cudaStreamWaitEvent(s2, evFork, 0);

  // side stream: bf16 prep for the attention GEMM (overlaps LSTM chain)
  convA_kernel<<<(BT*512/4 + 255)/256, 256, 0, s2>>>(enc_outs);
  convW_kernel<<<dim3(16,32), 256, 0, s2>>>(aw2g, aw2c);
  cudaEventRecord(evJ1, s2);

  // main stream: init + LSTM chain (pw kernels moved off critical path)
  init_kernel<<<(INIT_TOTAL+255)/256, 256>>>(b1, b2, bh, bg);

  GArgs az1; az1.A0=lha; az1.A1=h1; az1.W0=k1; az1.W1=r1;
  az1.xidx=x; az1.emb=emb; az1.C=p_z1; az1.K=1324; az1.N=2048;
  gemm16_atomic<V_Z1><<<dim3(4,42),128>>>(az1);
  cudaEventRecord(evZ1, 0);

  // side: h1n/c1n outputs
  cudaStreamWaitEvent(s2, evZ1, 0);
  lstm_pw_kernel<<<32,256,0,s2>>>(p_z1, c1, out_h1n, out_c1n);

  // main: z2 with inline h1n
  GArgs az2; az2.A0=p_z1; az2.A1=h2; az2.W0=k2; az2.W1=r2;
  az2.xidx=nullptr; az2.emb=c1; az2.C=p_z2; az2.K=1024; az2.N=2048;
  gemm16_atomic<V_Z2><<<dim3(4,32),128>>>(az2);
  cudaEventRecord(evZ2, 0);

  // side: h2n/c2n outputs
  cudaStreamWaitEvent(s2, evZ2, 0);
  lstm_pw_kernel<<<32,256,0,s2>>>(p_z2, c2, out_h2n, out_c2n);
  cudaEventRecord(evPW2, s2);

  // main: q with inline h2n
  GArgs aq; aq.A0=p_z2; aq.A1=nullptr; aq.W0=aw1g; aq.W1=aw1c;
  aq.xidx=nullptr; aq.emb=c2; aq.C=p_q; aq.K=512; aq.N=1024;
  gemm16_atomic<V_Q><<<dim3(2,16),128>>>(aq);

  // join: need bf16 enc/W for mma
  cudaStreamWaitEvent(0, evJ1, 0);
  mma_attn_scores_kernel<<<dim3(75,8), 256>>>(avg, avc);

  softmax_kernel<<<BB,256>>>();
  cudaEventRecord(evSoft, 0);

  // side stream: big copy pass as soon as align_c is ready
  cudaStreamWaitEvent(s2, evSoft, 0);
  copy_kernel<<<dim3((VV+511)/512, BB), 512, 0, s2>>>(enc_ins, out_result);
  cudaEventRecord(evCopy, s2);

  // main stream: gen-prob chain (overlaps the copy stream)
  ctx_kernel<<<dim3(10,BB),512>>>(enc_outs);

  // aha reads out_h2n -> join on pw2
  cudaStreamWaitEvent(0, evPW2, 0);
  GArgs aha; aha.A0=p_ctx; aha.A1=out_h2n; aha.W0=Wh; aha.W1=nullptr;
  aha.xidx=nullptr; aha.emb=nullptr; aha.C=p_ha; aha.K=1024; aha.N=512;
  gemm16_atomic<V_HA><<<dim3(1,32),128>>>(aha);
  ha_finalize_kernel<<<BB,512>>>(out_hidden, Wf, bf);

  gemm16_logits_split<<<dim3(40,8),128>>>(out_hidden, Wg);
  vred1_kernel<<<dim3(10,BB),256>>>();
  vred2_kernel<<<BB,32>>>();

  // join 2: copy must be in result before mixing
  cudaStreamWaitEvent(0, evCopy, 0);
  mix_kernel<<<dim3((VV+511)/512, BB), 512>>>(out_result);
}